// round 2
// baseline (speedup 1.0000x reference)
#include <cuda_runtime.h>
#include <math.h>

// ---------------------------------------------------------------------------
// Problem dims
//   B=4, S=2048, D=1024, H=16, DH=32, DP=64, DFF=4096
//   BS = B*S = 8192
// ---------------------------------------------------------------------------
#define BSZ   4
#define SEQ   2048
#define DIM   1024
#define NH    16
#define DHB   32
#define DPH   64
#define DFF   4096
#define BSROWS 8192   // B*S

// ---------------------------------------------------------------------------
// Scratch (device globals; no allocation allowed in kernel_launch)
// ---------------------------------------------------------------------------
__device__ float g_ln [8388608];     // LN output (reused for LN1 & LN2)   32MB
__device__ float g_v  [8388608];     // v = LN1(x)@W_in + b_in             32MB
__device__ float g_A2 [1048576];     // A transposed to [h][p][(i,j)]       4MB
__device__ float g_M  [134217728];   // M[h][bs][(i,j)]                   537MB
__device__ float g_hs [4194304];     // recurrence output [bs][H*DH]       16MB
__device__ float g_x2 [8388608];     // x + hs@W_out + b_out               32MB
__device__ float g_ffn[33554432];    // GELU(LN2@W1+b1)                   134MB

// ---------------------------------------------------------------------------
// Helpers
// ---------------------------------------------------------------------------
__device__ __forceinline__ float gelu_exact(float x) {
    return 0.5f * x * (1.0f + erff(x * 0.70710678118654752f));
}

__device__ __forceinline__ void cp16(unsigned dst, const void* src) {
    asm volatile("cp.async.ca.shared.global [%0], [%1], 16;" :: "r"(dst), "l"(src));
}

// ---------------------------------------------------------------------------
// A[h][i][p][j]  ->  A2[h][p][i*32+j]   (so M-GEMM B operand is row-major)
// ---------------------------------------------------------------------------
__global__ void prep_A2_kernel(const float* __restrict__ A, float* __restrict__ A2) {
    int idx = blockIdx.x * 256 + threadIdx.x;          // < 16*32*64*32 = 1048576
    int j = idx & 31;
    int p = (idx >> 5) & 63;
    int i = (idx >> 11) & 31;
    int h = idx >> 16;
    A2[((h * 64 + p) << 10) + (i << 5) + j] = A[idx];  // A is (h,i,p,j)-ordered = idx
}

// ---------------------------------------------------------------------------
// LayerNorm over last dim (1024). One block per row, 256 threads.
// ---------------------------------------------------------------------------
__global__ void ln_kernel(const float* __restrict__ x, const float* __restrict__ g,
                          const float* __restrict__ b, float* __restrict__ y) {
    int row = blockIdx.x;
    int tid = threadIdx.x;
    const float* xr = x + (size_t)row * DIM;
    float v[4];
    float s = 0.f, sq = 0.f;
#pragma unroll
    for (int i = 0; i < 4; i++) {
        v[i] = xr[tid + i * 256];
        s  += v[i];
        sq += v[i] * v[i];
    }
#pragma unroll
    for (int o = 16; o > 0; o >>= 1) {
        s  += __shfl_xor_sync(0xffffffffu, s,  o);
        sq += __shfl_xor_sync(0xffffffffu, sq, o);
    }
    __shared__ float ss[8], sqq[8];
    int w = tid >> 5, l = tid & 31;
    if (l == 0) { ss[w] = s; sqq[w] = sq; }
    __syncthreads();
    if (w == 0) {
        s  = (l < 8) ? ss[l]  : 0.f;
        sq = (l < 8) ? sqq[l] : 0.f;
#pragma unroll
        for (int o = 4; o > 0; o >>= 1) {
            s  += __shfl_xor_sync(0xffffffffu, s,  o);
            sq += __shfl_xor_sync(0xffffffffu, sq, o);
        }
        if (l == 0) { ss[0] = s; sqq[0] = sq; }
    }
    __syncthreads();
    s = ss[0]; sq = sqq[0];
    float mean = s * (1.0f / DIM);
    float var  = sq * (1.0f / DIM) - mean * mean;
    float rstd = rsqrtf(var + 1e-5f);
    float* yr = y + (size_t)row * DIM;
#pragma unroll
    for (int i = 0; i < 4; i++) {
        int c = tid + i * 256;
        yr[c] = (v[i] - mean) * rstd * g[c] + b[c];
    }
}

// ---------------------------------------------------------------------------
// Tiled fp32 GEMM: C = A(MxK) * B(KxN) [+bias] [+residual] [gelu]
// 64x64 tile, BK=16, 256 threads, 4x4 per-thread register tile.
// EPI bit0=bias, bit1=residual-add, bit2=gelu (gelu applied before residual).
// Requires M%64==0, N%64==0, K%16==0 (all shapes here satisfy this).
// Batched via blockIdx.z with element strides.
// ---------------------------------------------------------------------------
template <int EPI>
__global__ void __launch_bounds__(256) sgemm_kernel(
    const float* __restrict__ A, const float* __restrict__ B,
    float* __restrict__ C,
    const float* __restrict__ bias, const float* __restrict__ res,
    int M, int N, int K, int lda, int ldb, int ldc,
    size_t batchA, size_t batchB, size_t batchC)
{
    A += (size_t)blockIdx.z * batchA;
    B += (size_t)blockIdx.z * batchB;
    C += (size_t)blockIdx.z * batchC;

    __shared__ float As[16][65];   // padded to kill store conflicts
    __shared__ float Bs[16][64];

    int tid = threadIdx.x;
    int tx = tid & 15, ty = tid >> 4;
    int m0 = blockIdx.y * 64, n0 = blockIdx.x * 64;

    int arow = tid >> 2;            // 0..63
    int acol = (tid & 3) * 4;       // 0,4,8,12
    int brow = tid >> 4;            // 0..15
    int bcol = (tid & 15) * 4;      // 0..60

    const float* Aptr = A + (size_t)(m0 + arow) * lda + acol;
    const float* Bptr = B + (size_t)brow * ldb + n0 + bcol;

    float acc[4][4];
#pragma unroll
    for (int r = 0; r < 4; r++)
#pragma unroll
        for (int c = 0; c < 4; c++) acc[r][c] = 0.f;

    for (int k0 = 0; k0 < K; k0 += 16) {
        float4 av = *(const float4*)(Aptr + k0);
        float4 bv = *(const float4*)(Bptr + (size_t)k0 * ldb);
        __syncthreads();
        As[acol + 0][arow] = av.x;
        As[acol + 1][arow] = av.y;
        As[acol + 2][arow] = av.z;
        As[acol + 3][arow] = av.w;
        *(float4*)&Bs[brow][bcol] = bv;
        __syncthreads();
#pragma unroll
        for (int kk = 0; kk < 16; kk++) {
            float a0 = As[kk][ty * 4 + 0];
            float a1 = As[kk][ty * 4 + 1];
            float a2 = As[kk][ty * 4 + 2];
            float a3 = As[kk][ty * 4 + 3];
            float4 bq = *(const float4*)&Bs[kk][tx * 4];
            acc[0][0] = fmaf(a0, bq.x, acc[0][0]); acc[0][1] = fmaf(a0, bq.y, acc[0][1]);
            acc[0][2] = fmaf(a0, bq.z, acc[0][2]); acc[0][3] = fmaf(a0, bq.w, acc[0][3]);
            acc[1][0] = fmaf(a1, bq.x, acc[1][0]); acc[1][1] = fmaf(a1, bq.y, acc[1][1]);
            acc[1][2] = fmaf(a1, bq.z, acc[1][2]); acc[1][3] = fmaf(a1, bq.w, acc[1][3]);
            acc[2][0] = fmaf(a2, bq.x, acc[2][0]); acc[2][1] = fmaf(a2, bq.y, acc[2][1]);
            acc[2][2] = fmaf(a2, bq.z, acc[2][2]); acc[2][3] = fmaf(a2, bq.w, acc[2][3]);
            acc[3][0] = fmaf(a3, bq.x, acc[3][0]); acc[3][1] = fmaf(a3, bq.y, acc[3][1]);
            acc[3][2] = fmaf(a3, bq.z, acc[3][2]); acc[3][3] = fmaf(a3, bq.w, acc[3][3]);
        }
    }

    int n = n0 + tx * 4;
    float4 bv4;
    if (EPI & 1) bv4 = *(const float4*)(bias + n);
#pragma unroll
    for (int rr = 0; rr < 4; rr++) {
        size_t off = (size_t)(m0 + ty * 4 + rr) * ldc + n;
        float4 c = make_float4(acc[rr][0], acc[rr][1], acc[rr][2], acc[rr][3]);
        if (EPI & 1) { c.x += bv4.x; c.y += bv4.y; c.z += bv4.z; c.w += bv4.w; }
        if (EPI & 4) {
            c.x = gelu_exact(c.x); c.y = gelu_exact(c.y);
            c.z = gelu_exact(c.z); c.w = gelu_exact(c.w);
        }
        if (EPI & 2) {
            float4 rv = *(const float4*)(res + off);
            c.x += rv.x; c.y += rv.y; c.z += rv.z; c.w += rv.w;
        }
        *(float4*)(C + off) = c;
    }
}

// ---------------------------------------------------------------------------
// Sequential MPS recurrence. One CTA per (b,h) chain (64 CTAs).
// 128 threads: all threads prefetch the next M tile (4KB) via cp.async;
// warp 0 computes h_new = tanh(h @ M_s) with h kept in registers (lane j
// holds h_j) and broadcast via shuffles.
// M layout: g_M[h][b*2048+s][i*32+j]
// hs layout: g_hs[b*2048+s][h*32+j]
// ---------------------------------------------------------------------------
__global__ void __launch_bounds__(128, 1) recurrence_kernel(
    const float* __restrict__ Mg, float* __restrict__ hs)
{
    __shared__ __align__(16) float sm[2][1024];
    int tid = threadIdx.x;
    int b = blockIdx.x >> 4;
    int h = blockIdx.x & 15;
    const float* Mbh = Mg + ((size_t)h * BSROWS + (size_t)b * SEQ) * 1024;
    unsigned s0 = (unsigned)__cvta_generic_to_shared(&sm[0][0]);

    // preload tile 0
    {
        unsigned dst = s0 + tid * 32;
        const float* src = Mbh + tid * 8;
        cp16(dst, src);
        cp16(dst + 16, src + 4);
        asm volatile("cp.async.commit_group;");
        asm volatile("cp.async.wait_group 0;");
    }
    __syncthreads();

    float r = 0.17677669529663688f;   // 1/sqrt(32)
    float* hsb = hs + ((size_t)b * SEQ) * 512 + h * 32 + (tid & 31);

    for (int s = 0; s < SEQ; ++s) {
        int buf = s & 1;
        if (s + 1 < SEQ) {
            unsigned dst = s0 + (unsigned)((buf ^ 1) * 4096) + tid * 32;
            const float* src = Mbh + (size_t)(s + 1) * 1024 + tid * 8;
            cp16(dst, src);
            cp16(dst + 16, src + 4);
        }
        asm volatile("cp.async.commit_group;");
        if (tid < 32) {
            const float* ms = sm[buf];
            float a0 = 0.f, a1 = 0.f, a2 = 0.f, a3 = 0.f;
#pragma unroll
            for (int i = 0; i < 32; i += 4) {
                a0 = fmaf(__shfl_sync(0xffffffffu, r, i + 0), ms[(i + 0) * 32 + tid], a0);
                a1 = fmaf(__shfl_sync(0xffffffffu, r, i + 1), ms[(i + 1) * 32 + tid], a1);
                a2 = fmaf(__shfl_sync(0xffffffffu, r, i + 2), ms[(i + 2) * 32 + tid], a2);
                a3 = fmaf(__shfl_sync(0xffffffffu, r, i + 3), ms[(i + 3) * 32 + tid], a3);
            }
            r = tanhf((a0 + a1) + (a2 + a3));
            hsb[(size_t)s * 512] = r;
        }
        asm volatile("cp.async.wait_group 0;");
        __syncthreads();
    }
}

// ---------------------------------------------------------------------------
// Launch
// Inputs (metadata order):
//  0 x         [4,2048,1024]     1 ln1_g [1024]   2 ln1_b [1024]
//  3 W_in      [1024,1024]       4 b_in  [1024]
//  5 A         [16,32,64,32]
//  6 W_out     [512,1024]        7 b_out [1024]
//  8 ln2_g     [1024]            9 ln2_b [1024]
// 10 W1        [1024,4096]      11 b1    [4096]
// 12 W2        [4096,1024]      13 b2    [1024]
// Output: [4,2048,1024] fp32
// ---------------------------------------------------------------------------
extern "C" void kernel_launch(void* const* d_in, const int* in_sizes, int n_in,
                              void* d_out, int out_size)
{
    const float* x     = (const float*)d_in[0];
    const float* ln1_g = (const float*)d_in[1];
    const float* ln1_b = (const float*)d_in[2];
    const float* W_in  = (const float*)d_in[3];
    const float* b_in  = (const float*)d_in[4];
    const float* A     = (const float*)d_in[5];
    const float* W_out = (const float*)d_in[6];
    const float* b_out = (const float*)d_in[7];
    const float* ln2_g = (const float*)d_in[8];
    const float* ln2_b = (const float*)d_in[9];
    const float* W1    = (const float*)d_in[10];
    const float* b1    = (const float*)d_in[11];
    const float* W2    = (const float*)d_in[12];
    const float* b2    = (const float*)d_in[13];
    float* out = (float*)d_out;

    float *ln, *v, *A2, *M, *hsp, *x2, *ffn;
    cudaGetSymbolAddress((void**)&ln,  g_ln);
    cudaGetSymbolAddress((void**)&v,   g_v);
    cudaGetSymbolAddress((void**)&A2,  g_A2);
    cudaGetSymbolAddress((void**)&M,   g_M);
    cudaGetSymbolAddress((void**)&hsp, g_hs);
    cudaGetSymbolAddress((void**)&x2,  g_x2);
    cudaGetSymbolAddress((void**)&ffn, g_ffn);

    // 1) A -> A2 transpose
    prep_A2_kernel<<<4096, 256>>>(A, A2);

    // 2) LN1
    ln_kernel<<<BSROWS, 256>>>(x, ln1_g, ln1_b, ln);

    // 3) v = ln @ W_in + b_in        [8192,1024,1024]
    sgemm_kernel<1><<<dim3(DIM / 64, BSROWS / 64, 1), 256>>>(
        ln, W_in, v, b_in, nullptr,
        BSROWS, DIM, DIM, DIM, DIM, DIM, 0, 0, 0);

    // 4) M[h] = v[:,h*64:(h+1)*64] @ A2[h]   batched over 16 heads
    //    [8192,1024,64] each
    sgemm_kernel<0><<<dim3(1024 / 64, BSROWS / 64, NH), 256>>>(
        v, A2, M, nullptr, nullptr,
        BSROWS, 1024, DPH, DIM, 1024, 1024,
        (size_t)DPH, (size_t)DPH * 1024, (size_t)BSROWS * 1024);

    // 5) sequential recurrence -> hs
    recurrence_kernel<<<64, 128>>>(M, hsp);

    // 6) x2 = x + hs @ W_out + b_out   [8192,1024,512]
    sgemm_kernel<3><<<dim3(DIM / 64, BSROWS / 64, 1), 256>>>(
        hsp, W_out, x2, b_out, x,
        BSROWS, DIM, NH * DHB, NH * DHB, DIM, DIM, 0, 0, 0);

    // 7) LN2
    ln_kernel<<<BSROWS, 256>>>(x2, ln2_g, ln2_b, ln);

    // 8) ffn = gelu(ln @ W1 + b1)      [8192,4096,1024]
    sgemm_kernel<5><<<dim3(DFF / 64, BSROWS / 64, 1), 256>>>(
        ln, W1, ffn, b1, nullptr,
        BSROWS, DFF, DIM, DIM, DFF, DFF, 0, 0, 0);

    // 9) out = x2 + ffn @ W2 + b2      [8192,1024,4096]
    sgemm_kernel<3><<<dim3(DIM / 64, BSROWS / 64, 1), 256>>>(
        ffn, W2, out, b2, x2,
        BSROWS, DIM, DFF, DFF, DIM, DIM, 0, 0, 0);
}

// round 4
// speedup vs baseline: 2.1258x; 2.1258x over previous
#include <cuda_runtime.h>
#include <math.h>
#include <cstdint>

#define BSROWS 8192
#define SEQ    2048
#define DIM    1024
#define NH     16
#define DFF    4096

// ---------------------------------------------------------------------------
// Scratch (device globals)
// ---------------------------------------------------------------------------
__device__ float g_ln   [8388608];    // LN output (tf32-rounded)
__device__ float g_v    [8388608];    // v = LN1(x)@W_in + b_in (tf32-rounded)
__device__ float g_a2   [1048576];    // A rearranged [h][p][(i,j)] (tf32)
__device__ float g_M    [134217728];  // M[h][bs][(i,j)] fp32
__device__ float g_hs   [4194304];    // recurrence out [bs][H*DH] (tf32)
__device__ float g_x2   [8388608];    // x + hs@W_out + b_out (fp32)
__device__ float g_ffn  [33554432];   // GELU(LN2@W1+b1) (tf32-rounded)
__device__ float g_winc [1048576];    // tf32(W_in)  [1024][1024]
__device__ float g_woutc[524288];     // tf32(W_out) [512][1024]
__device__ float g_w1c  [4194304];    // tf32(W1)    [1024][4096]
__device__ float g_w2c  [4194304];    // tf32(W2)    [4096][1024]

// ---------------------------------------------------------------------------
// Helpers
// ---------------------------------------------------------------------------
__device__ __forceinline__ uint32_t smem_u32(const void* p) {
    return (uint32_t)__cvta_generic_to_shared(p);
}
__device__ __forceinline__ float gelu_exact(float x) {
    return 0.5f * x * (1.0f + erff(x * 0.70710678118654752f));
}
__device__ __forceinline__ void cp16(uint32_t dst, const void* src) {
    asm volatile("cp.async.ca.shared.global [%0], [%1], 16;" :: "r"(dst), "l"(src));
}
__device__ __forceinline__ float tf32r(float x) {
    uint32_t t;
    asm("cvt.rna.tf32.f32 %0, %1;" : "=r"(t) : "f"(x));
    return __uint_as_float(t);
}
__device__ __forceinline__ void mma_tf32(float* d, const float* a, const float* b) {
    asm volatile(
        "mma.sync.aligned.m16n8k8.row.col.f32.tf32.tf32.f32 "
        "{%0,%1,%2,%3}, {%4,%5,%6,%7}, {%8,%9}, {%0,%1,%2,%3};"
        : "+f"(d[0]), "+f"(d[1]), "+f"(d[2]), "+f"(d[3])
        : "r"(__float_as_uint(a[0])), "r"(__float_as_uint(a[1])),
          "r"(__float_as_uint(a[2])), "r"(__float_as_uint(a[3])),
          "r"(__float_as_uint(b[0])), "r"(__float_as_uint(b[1])));
}

// ---------------------------------------------------------------------------
// prep: A[h][i][p][j] -> A2[h][p][i*32+j]  (tf32-rounded)
// ---------------------------------------------------------------------------
__global__ void prep_A2_kernel(const float* __restrict__ A, float* __restrict__ A2) {
    int idx = blockIdx.x * 256 + threadIdx.x;
    int j = idx & 31;
    int p = (idx >> 5) & 63;
    int i = (idx >> 11) & 31;
    int h = idx >> 16;
    A2[((h * 64 + p) << 10) + (i << 5) + j] = tf32r(A[idx]);
}

// ---------------------------------------------------------------------------
// tf32-rounding copy (weights)
// ---------------------------------------------------------------------------
__global__ void cvt_copy_kernel(const float* __restrict__ in, float* __restrict__ out, int n4) {
    int i = blockIdx.x * 256 + threadIdx.x;
    if (i < n4) {
        float4 v = ((const float4*)in)[i];
        v.x = tf32r(v.x); v.y = tf32r(v.y); v.z = tf32r(v.z); v.w = tf32r(v.w);
        ((float4*)out)[i] = v;
    }
}

// ---------------------------------------------------------------------------
// LayerNorm over last dim (1024), output tf32-rounded (feeds mma only).
// ---------------------------------------------------------------------------
__global__ void ln_kernel(const float* __restrict__ x, const float* __restrict__ g,
                          const float* __restrict__ b, float* __restrict__ y) {
    int row = blockIdx.x;
    int tid = threadIdx.x;
    const float* xr = x + (size_t)row * DIM;
    float v[4];
    float s = 0.f, sq = 0.f;
#pragma unroll
    for (int i = 0; i < 4; i++) {
        v[i] = xr[tid + i * 256];
        s  += v[i];
        sq += v[i] * v[i];
    }
#pragma unroll
    for (int o = 16; o > 0; o >>= 1) {
        s  += __shfl_xor_sync(0xffffffffu, s,  o);
        sq += __shfl_xor_sync(0xffffffffu, sq, o);
    }
    __shared__ float ss[8], sqq[8];
    int w = tid >> 5, l = tid & 31;
    if (l == 0) { ss[w] = s; sqq[w] = sq; }
    __syncthreads();
    if (w == 0) {
        s  = (l < 8) ? ss[l]  : 0.f;
        sq = (l < 8) ? sqq[l] : 0.f;
#pragma unroll
        for (int o = 4; o > 0; o >>= 1) {
            s  += __shfl_xor_sync(0xffffffffu, s,  o);
            sq += __shfl_xor_sync(0xffffffffu, sq, o);
        }
        if (l == 0) { ss[0] = s; sqq[0] = sq; }
    }
    __syncthreads();
    s = ss[0]; sq = sqq[0];
    float mean = s * (1.0f / DIM);
    float var  = sq * (1.0f / DIM) - mean * mean;
    float rstd = rsqrtf(var + 1e-5f);
    float* yr = y + (size_t)row * DIM;
#pragma unroll
    for (int i = 0; i < 4; i++) {
        int c = tid + i * 256;
        yr[c] = tf32r((v[i] - mean) * rstd * g[c] + b[c]);
    }
}

// ---------------------------------------------------------------------------
// tf32 warp-MMA GEMM: C[M,N] = A[M,K] @ B[K,N]
// A row-major [M][K], B row-major [K][N] (original weight layout).
// CTA tile 128x128, BK=16, 256 thr (8 warps, 2x4, warp tile 64x32),
// mma.sync.m16n8k8, cp.async double buffer.
// EPI: bit0=bias, bit1=residual, bit2=gelu, bit3=tf32-round output.
// Requires M%128==0, N%128==0, K%16==0.
// ---------------------------------------------------------------------------
template <int EPI>
__global__ void __launch_bounds__(256, 2) tc_gemm(
    const float* __restrict__ A, const float* __restrict__ B, float* __restrict__ C,
    const float* __restrict__ bias, const float* __restrict__ res,
    int K, int lda, int ldb, int ldc,
    size_t batchA, size_t batchB, size_t batchC)
{
    __shared__ float As[2][128][20];   // [m][k], stride 20 -> conflict-free frags
    __shared__ float Bs[2][16][136];   // [k][n], stride 136 -> conflict-free frags

    A += (size_t)blockIdx.z * batchA;
    B += (size_t)blockIdx.z * batchB;
    C += (size_t)blockIdx.z * batchC;

    const int tid = threadIdx.x;
    const int m0 = blockIdx.y * 128, n0 = blockIdx.x * 128;
    const int wid = tid >> 5, lane = tid & 31;
    const int wm = (wid >> 2) * 64;     // 0 / 64
    const int wn = (wid & 3) * 32;      // 0,32,64,96
    const int gq = lane >> 2, tg = lane & 3;

    const uint32_t sA = smem_u32(&As[0][0][0]);
    const uint32_t sB = smem_u32(&Bs[0][0][0]);

    // global->smem loaders
    const int arow = tid >> 1, ahalf = tid & 1;          // A: 128 rows x 16 k
    const int brow = tid >> 4, bseg = tid & 15;          // B: 16 rows x 128 n

    auto loadA = [&](int buf, int k0) {
        const float* src = A + (size_t)(m0 + arow) * lda + k0 + ahalf * 8;
        uint32_t dst = sA + (uint32_t)buf * 10240 + (uint32_t)arow * 80 + (uint32_t)ahalf * 32;
        cp16(dst, src);
        cp16(dst + 16, src + 4);
    };
    auto loadB = [&](int buf, int k0) {
        const float* src = B + (size_t)(k0 + brow) * ldb + n0 + bseg * 8;
        uint32_t dst = sB + (uint32_t)buf * 8704 + (uint32_t)brow * 544 + (uint32_t)bseg * 32;
        cp16(dst, src);
        cp16(dst + 16, src + 4);
    };

    float acc[4][4][4];
#pragma unroll
    for (int mi = 0; mi < 4; mi++)
#pragma unroll
        for (int ni = 0; ni < 4; ni++)
#pragma unroll
            for (int q = 0; q < 4; q++) acc[mi][ni][q] = 0.f;

    const int KT = K >> 4;
    loadA(0, 0);
    loadB(0, 0);
    asm volatile("cp.async.commit_group;");

    for (int kt = 0; kt < KT; ++kt) {
        const int buf = kt & 1;
        asm volatile("cp.async.wait_group 0;");
        __syncthreads();
        if (kt + 1 < KT) {
            loadA(buf ^ 1, (kt + 1) * 16);
            loadB(buf ^ 1, (kt + 1) * 16);
            asm volatile("cp.async.commit_group;");
        }
#pragma unroll
        for (int kk = 0; kk < 16; kk += 8) {
            float a[4][4], b[4][2];
#pragma unroll
            for (int mi = 0; mi < 4; mi++) {
                const int m = wm + mi * 16;
                a[mi][0] = As[buf][m + gq][kk + tg];
                a[mi][1] = As[buf][m + gq + 8][kk + tg];
                a[mi][2] = As[buf][m + gq][kk + tg + 4];
                a[mi][3] = As[buf][m + gq + 8][kk + tg + 4];
            }
#pragma unroll
            for (int ni = 0; ni < 4; ni++) {
                const int n = wn + ni * 8;
                b[ni][0] = Bs[buf][kk + tg][n + gq];
                b[ni][1] = Bs[buf][kk + tg + 4][n + gq];
            }
#pragma unroll
            for (int mi = 0; mi < 4; mi++)
#pragma unroll
                for (int ni = 0; ni < 4; ni++)
                    mma_tf32(acc[mi][ni], a[mi], b[ni]);
        }
    }

    // epilogue
#pragma unroll
    for (int mi = 0; mi < 4; mi++) {
        const int r0 = m0 + wm + mi * 16 + gq;
#pragma unroll
        for (int ni = 0; ni < 4; ni++) {
            const int c = n0 + wn + ni * 8 + 2 * tg;
            float2 v01 = make_float2(acc[mi][ni][0], acc[mi][ni][1]);
            float2 v23 = make_float2(acc[mi][ni][2], acc[mi][ni][3]);
            if (EPI & 1) {
                float2 bv = *(const float2*)(bias + c);
                v01.x += bv.x; v01.y += bv.y;
                v23.x += bv.x; v23.y += bv.y;
            }
            if (EPI & 4) {
                v01.x = gelu_exact(v01.x); v01.y = gelu_exact(v01.y);
                v23.x = gelu_exact(v23.x); v23.y = gelu_exact(v23.y);
            }
            size_t off0 = (size_t)r0 * ldc + c;
            size_t off1 = (size_t)(r0 + 8) * ldc + c;
            if (EPI & 2) {
                float2 q0 = *(const float2*)(res + off0);
                float2 q1 = *(const float2*)(res + off1);
                v01.x += q0.x; v01.y += q0.y;
                v23.x += q1.x; v23.y += q1.y;
            }
            if (EPI & 8) {
                v01.x = tf32r(v01.x); v01.y = tf32r(v01.y);
                v23.x = tf32r(v23.x); v23.y = tf32r(v23.y);
            }
            *(float2*)(C + off0) = v01;
            *(float2*)(C + off1) = v23;
        }
    }
}

// ---------------------------------------------------------------------------
// Sequential MPS recurrence. One CTA per (b,h) chain (64 CTAs).
// ---------------------------------------------------------------------------
__global__ void __launch_bounds__(128, 1) recurrence_kernel(
    const float* __restrict__ Mg, float* __restrict__ hs)
{
    __shared__ __align__(16) float sm[2][1024];
    int tid = threadIdx.x;
    int b = blockIdx.x >> 4;
    int h = blockIdx.x & 15;
    const float* Mbh = Mg + ((size_t)h * BSROWS + (size_t)b * SEQ) * 1024;
    unsigned s0 = smem_u32(&sm[0][0]);

    {
        unsigned dst = s0 + tid * 32;
        const float* src = Mbh + tid * 8;
        cp16(dst, src);
        cp16(dst + 16, src + 4);
        asm volatile("cp.async.commit_group;");
        asm volatile("cp.async.wait_group 0;");
    }
    __syncthreads();

    float r = 0.17677669529663688f;   // 1/sqrt(32)
    float* hsb = hs + ((size_t)b * SEQ) * 512 + h * 32 + (tid & 31);

    for (int s = 0; s < SEQ; ++s) {
        int buf = s & 1;
        if (s + 1 < SEQ) {
            unsigned dst = s0 + (unsigned)((buf ^ 1) * 4096) + tid * 32;
            const float* src = Mbh + (size_t)(s + 1) * 1024 + tid * 8;
            cp16(dst, src);
            cp16(dst + 16, src + 4);
        }
        asm volatile("cp.async.commit_group;");
        if (tid < 32) {
            const float* ms = sm[buf];
            float a0 = 0.f, a1 = 0.f, a2 = 0.f, a3 = 0.f;
#pragma unroll
            for (int i = 0; i < 32; i += 4) {
                a0 = fmaf(__shfl_sync(0xffffffffu, r, i + 0), ms[(i + 0) * 32 + tid], a0);
                a1 = fmaf(__shfl_sync(0xffffffffu, r, i + 1), ms[(i + 1) * 32 + tid], a1);
                a2 = fmaf(__shfl_sync(0xffffffffu, r, i + 2), ms[(i + 2) * 32 + tid], a2);
                a3 = fmaf(__shfl_sync(0xffffffffu, r, i + 3), ms[(i + 3) * 32 + tid], a3);
            }
            r = tanhf((a0 + a1) + (a2 + a3));
            hsb[(size_t)s * 512] = tf32r(r);
        }
        asm volatile("cp.async.wait_group 0;");
        __syncthreads();
    }
}

// ---------------------------------------------------------------------------
// Launch
// ---------------------------------------------------------------------------
extern "C" void kernel_launch(void* const* d_in, const int* in_sizes, int n_in,
                              void* d_out, int out_size)
{
    const float* x     = (const float*)d_in[0];
    const float* ln1_g = (const float*)d_in[1];
    const float* ln1_b = (const float*)d_in[2];
    const float* W_in  = (const float*)d_in[3];
    const float* b_in  = (const float*)d_in[4];
    const float* A     = (const float*)d_in[5];
    const float* W_out = (const float*)d_in[6];
    const float* b_out = (const float*)d_in[7];
    const float* ln2_g = (const float*)d_in[8];
    const float* ln2_b = (const float*)d_in[9];
    const float* W1    = (const float*)d_in[10];
    const float* b1    = (const float*)d_in[11];
    const float* W2    = (const float*)d_in[12];
    const float* b2    = (const float*)d_in[13];
    float* out = (float*)d_out;

    float *ln, *v, *a2, *M, *hsp, *x2, *ffn, *winc, *woutc, *w1c, *w2c;
    cudaGetSymbolAddress((void**)&ln,    g_ln);
    cudaGetSymbolAddress((void**)&v,     g_v);
    cudaGetSymbolAddress((void**)&a2,    g_a2);
    cudaGetSymbolAddress((void**)&M,     g_M);
    cudaGetSymbolAddress((void**)&hsp,   g_hs);
    cudaGetSymbolAddress((void**)&x2,    g_x2);
    cudaGetSymbolAddress((void**)&ffn,   g_ffn);
    cudaGetSymbolAddress((void**)&winc,  g_winc);
    cudaGetSymbolAddress((void**)&woutc, g_woutc);
    cudaGetSymbolAddress((void**)&w1c,   g_w1c);
    cudaGetSymbolAddress((void**)&w2c,   g_w2c);

    // prep: tf32-rounded weight copies + A rearrange
    prep_A2_kernel<<<4096, 256>>>(A, a2);
    cvt_copy_kernel<<<1024, 256>>>(W_in,  winc,  1048576 / 4);
    cvt_copy_kernel<<<512,  256>>>(W_out, woutc, 524288 / 4);
    cvt_copy_kernel<<<4096, 256>>>(W1,    w1c,   4194304 / 4);
    cvt_copy_kernel<<<4096, 256>>>(W2,    w2c,   4194304 / 4);

    // LN1 (tf32-rounded output)
    ln_kernel<<<BSROWS, 256>>>(x, ln1_g, ln1_b, ln);

    // v = ln @ W_in + b_in   [8192 x 1024 x 1024], output tf32-rounded
    tc_gemm<9><<<dim3(8, 64, 1), 256>>>(
        ln, winc, v, b_in, nullptr, DIM, DIM, DIM, DIM, 0, 0, 0);

    // M[h] = v[:, h*64:(h+1)*64] @ A2[h]   16 heads, [8192 x 1024 x 64]
    tc_gemm<0><<<dim3(8, 64, NH), 256>>>(
        v, a2, M, nullptr, nullptr, 64, DIM, 1024, 1024,
        (size_t)64, (size_t)65536, (size_t)BSROWS * 1024);

    // sequential recurrence -> hs (tf32-rounded)
    recurrence_kernel<<<64, 128>>>(M, hsp);

    // x2 = x + hs @ W_out + b_out   [8192 x 1024 x 512]
    tc_gemm<3><<<dim3(8, 64, 1), 256>>>(
        hsp, woutc, x2, b_out, x, 512, 512, DIM, DIM, 0, 0, 0);

    // LN2 (tf32-rounded output)
    ln_kernel<<<BSROWS, 256>>>(x2, ln2_g, ln2_b, ln);

    // ffn = gelu(ln @ W1 + b1)  [8192 x 4096 x 1024], output tf32-rounded
    tc_gemm<13><<<dim3(32, 64, 1), 256>>>(
        ln, w1c, ffn, b1, nullptr, DIM, DIM, DFF, DFF, 0, 0, 0);

    // out = x2 + ffn @ W2 + b2  [8192 x 1024 x 4096]
    tc_gemm<3><<<dim3(8, 64, 1), 256>>>(
        ffn, w2c, out, b2, x2, DFF, DFF, DIM, DIM, 0, 0, 0);
}

// round 5
// speedup vs baseline: 2.1275x; 1.0008x over previous
#include <cuda_runtime.h>
#include <math.h>
#include <cstdint>

#define BSROWS 8192
#define SEQ    2048
#define DIM    1024
#define NH     16
#define DFF    4096

// ---------------------------------------------------------------------------
// Scratch (device globals)
// ---------------------------------------------------------------------------
__device__ float g_ln   [8388608];    // LN output (tf32-rounded)
__device__ float g_v    [8388608];    // v = LN1(x)@W_in + b_in (tf32-rounded)
__device__ float g_a2   [1048576];    // A rearranged [h][p][j*32+i] (tf32)
__device__ float g_M    [134217728];  // M[h][bs][j*32+i] fp32
__device__ float g_hs   [4194304];    // recurrence out [bs][H*DH] (tf32)
__device__ float g_x2   [8388608];    // x + hs@W_out + b_out (fp32)
__device__ float g_ffn  [33554432];   // GELU(LN2@W1+b1) (tf32-rounded)
__device__ float g_winc [1048576];    // tf32(W_in)  [1024][1024]
__device__ float g_woutc[524288];     // tf32(W_out) [512][1024]
__device__ float g_w1c  [4194304];    // tf32(W1)    [1024][4096]
__device__ float g_w2c  [4194304];    // tf32(W2)    [4096][1024]

// ---------------------------------------------------------------------------
// Helpers
// ---------------------------------------------------------------------------
__device__ __forceinline__ uint32_t smem_u32(const void* p) {
    return (uint32_t)__cvta_generic_to_shared(p);
}
__device__ __forceinline__ float gelu_exact(float x) {
    return 0.5f * x * (1.0f + erff(x * 0.70710678118654752f));
}
__device__ __forceinline__ void cp16(uint32_t dst, const void* src) {
    asm volatile("cp.async.cg.shared.global [%0], [%1], 16;" :: "r"(dst), "l"(src));
}
__device__ __forceinline__ float tf32r(float x) {
    uint32_t t;
    asm("cvt.rna.tf32.f32 %0, %1;" : "=r"(t) : "f"(x));
    return __uint_as_float(t);
}
__device__ __forceinline__ float tanh_fast(float x) {
    float r;
    asm("tanh.approx.f32 %0, %1;" : "=f"(r) : "f"(x));
    return r;
}
__device__ __forceinline__ void mma_tf32(float* d, const float* a, const float* b) {
    asm volatile(
        "mma.sync.aligned.m16n8k8.row.col.f32.tf32.tf32.f32 "
        "{%0,%1,%2,%3}, {%4,%5,%6,%7}, {%8,%9}, {%0,%1,%2,%3};"
        : "+f"(d[0]), "+f"(d[1]), "+f"(d[2]), "+f"(d[3])
        : "r"(__float_as_uint(a[0])), "r"(__float_as_uint(a[1])),
          "r"(__float_as_uint(a[2])), "r"(__float_as_uint(a[3])),
          "r"(__float_as_uint(b[0])), "r"(__float_as_uint(b[1])));
}

// ---------------------------------------------------------------------------
// Merged prep: A rearrange (scalar) + 4 weight tf32 copies (float4).
//   idx < 1048576                 : A[h][i][p][j] -> A2[h][p][j*32+i] (tf32)
//   then float4 ranges            : W_in, W_out, W1, W2 tf32 copies
// ---------------------------------------------------------------------------
__global__ void prep_kernel(const float* __restrict__ A, float* __restrict__ A2,
                            const float* __restrict__ Wi, float* __restrict__ Wic,
                            const float* __restrict__ Wo, float* __restrict__ Woc,
                            const float* __restrict__ W1, float* __restrict__ W1c,
                            const float* __restrict__ W2, float* __restrict__ W2c)
{
    int idx = blockIdx.x * 256 + threadIdx.x;
    if (idx < 1048576) {
        int j = idx & 31;
        int p = (idx >> 5) & 63;
        int i = (idx >> 11) & 31;
        int h = idx >> 16;
        A2[((h * 64 + p) << 10) + (j << 5) + i] = tf32r(A[idx]);
        return;
    }
    int t = idx - 1048576;
    const float* src; float* dst;
    if (t < 262144)            { src = Wi; dst = Wic; }
    else if ((t -= 262144) < 131072)  { src = Wo; dst = Woc; }
    else if ((t -= 131072) < 1048576) { src = W1; dst = W1c; }
    else if ((t -= 1048576) < 1048576){ src = W2; dst = W2c; }
    else return;
    float4 v = ((const float4*)src)[t];
    v.x = tf32r(v.x); v.y = tf32r(v.y); v.z = tf32r(v.z); v.w = tf32r(v.w);
    ((float4*)dst)[t] = v;
}

// ---------------------------------------------------------------------------
// LayerNorm over last dim (1024), output tf32-rounded.
// ---------------------------------------------------------------------------
__global__ void ln_kernel(const float* __restrict__ x, const float* __restrict__ g,
                          const float* __restrict__ b, float* __restrict__ y) {
    int row = blockIdx.x;
    int tid = threadIdx.x;
    const float* xr = x + (size_t)row * DIM;
    float v[4];
    float s = 0.f, sq = 0.f;
#pragma unroll
    for (int i = 0; i < 4; i++) {
        v[i] = xr[tid + i * 256];
        s  += v[i];
        sq += v[i] * v[i];
    }
#pragma unroll
    for (int o = 16; o > 0; o >>= 1) {
        s  += __shfl_xor_sync(0xffffffffu, s,  o);
        sq += __shfl_xor_sync(0xffffffffu, sq, o);
    }
    __shared__ float ss[8], sqq[8];
    int w = tid >> 5, l = tid & 31;
    if (l == 0) { ss[w] = s; sqq[w] = sq; }
    __syncthreads();
    if (w == 0) {
        s  = (l < 8) ? ss[l]  : 0.f;
        sq = (l < 8) ? sqq[l] : 0.f;
#pragma unroll
        for (int o = 4; o > 0; o >>= 1) {
            s  += __shfl_xor_sync(0xffffffffu, s,  o);
            sq += __shfl_xor_sync(0xffffffffu, sq, o);
        }
        if (l == 0) { ss[0] = s; sqq[0] = sq; }
    }
    __syncthreads();
    s = ss[0]; sq = sqq[0];
    float mean = s * (1.0f / DIM);
    float var  = sq * (1.0f / DIM) - mean * mean;
    float rstd = rsqrtf(var + 1e-5f);
    float* yr = y + (size_t)row * DIM;
#pragma unroll
    for (int i = 0; i < 4; i++) {
        int c = tid + i * 256;
        yr[c] = tf32r((v[i] - mean) * rstd * g[c] + b[c]);
    }
}

// ---------------------------------------------------------------------------
// tf32 warp-MMA GEMM (unchanged from R4 except .cg loads).
// C[M,N] = A[M,K] @ B[K,N]; CTA 128x128, BK=16, 8 warps (64x32 each),
// mma.sync.m16n8k8, cp.async double buffer.
// EPI: bit0=bias, bit1=residual, bit2=gelu, bit3=tf32-round output.
// ---------------------------------------------------------------------------
template <int EPI>
__global__ void __launch_bounds__(256, 2) tc_gemm(
    const float* __restrict__ A, const float* __restrict__ B, float* __restrict__ C,
    const float* __restrict__ bias, const float* __restrict__ res,
    int K, int lda, int ldb, int ldc,
    size_t batchA, size_t batchB, size_t batchC)
{
    __shared__ float As[2][128][20];
    __shared__ float Bs[2][16][136];

    A += (size_t)blockIdx.z * batchA;
    B += (size_t)blockIdx.z * batchB;
    C += (size_t)blockIdx.z * batchC;

    const int tid = threadIdx.x;
    const int m0 = blockIdx.y * 128, n0 = blockIdx.x * 128;
    const int wid = tid >> 5, lane = tid & 31;
    const int wm = (wid >> 2) * 64;
    const int wn = (wid & 3) * 32;
    const int gq = lane >> 2, tg = lane & 3;

    const uint32_t sA = smem_u32(&As[0][0][0]);
    const uint32_t sB = smem_u32(&Bs[0][0][0]);

    const int arow = tid >> 1, ahalf = tid & 1;
    const int brow = tid >> 4, bseg = tid & 15;

    auto loadA = [&](int buf, int k0) {
        const float* src = A + (size_t)(m0 + arow) * lda + k0 + ahalf * 8;
        uint32_t dst = sA + (uint32_t)buf * 10240 + (uint32_t)arow * 80 + (uint32_t)ahalf * 32;
        cp16(dst, src);
        cp16(dst + 16, src + 4);
    };
    auto loadB = [&](int buf, int k0) {
        const float* src = B + (size_t)(k0 + brow) * ldb + n0 + bseg * 8;
        uint32_t dst = sB + (uint32_t)buf * 8704 + (uint32_t)brow * 544 + (uint32_t)bseg * 32;
        cp16(dst, src);
        cp16(dst + 16, src + 4);
    };

    float acc[4][4][4];
#pragma unroll
    for (int mi = 0; mi < 4; mi++)
#pragma unroll
        for (int ni = 0; ni < 4; ni++)
#pragma unroll
            for (int q = 0; q < 4; q++) acc[mi][ni][q] = 0.f;

    const int KT = K >> 4;
    loadA(0, 0);
    loadB(0, 0);
    asm volatile("cp.async.commit_group;");

    for (int kt = 0; kt < KT; ++kt) {
        const int buf = kt & 1;
        asm volatile("cp.async.wait_group 0;");
        __syncthreads();
        if (kt + 1 < KT) {
            loadA(buf ^ 1, (kt + 1) * 16);
            loadB(buf ^ 1, (kt + 1) * 16);
            asm volatile("cp.async.commit_group;");
        }
#pragma unroll
        for (int kk = 0; kk < 16; kk += 8) {
            float a[4][4], b[4][2];
#pragma unroll
            for (int mi = 0; mi < 4; mi++) {
                const int m = wm + mi * 16;
                a[mi][0] = As[buf][m + gq][kk + tg];
                a[mi][1] = As[buf][m + gq + 8][kk + tg];
                a[mi][2] = As[buf][m + gq][kk + tg + 4];
                a[mi][3] = As[buf][m + gq + 8][kk + tg + 4];
            }
#pragma unroll
            for (int ni = 0; ni < 4; ni++) {
                const int n = wn + ni * 8;
                b[ni][0] = Bs[buf][kk + tg][n + gq];
                b[ni][1] = Bs[buf][kk + tg + 4][n + gq];
            }
#pragma unroll
            for (int mi = 0; mi < 4; mi++)
#pragma unroll
                for (int ni = 0; ni < 4; ni++)
                    mma_tf32(acc[mi][ni], a[mi], b[ni]);
        }
    }

#pragma unroll
    for (int mi = 0; mi < 4; mi++) {
        const int r0 = m0 + wm + mi * 16 + gq;
#pragma unroll
        for (int ni = 0; ni < 4; ni++) {
            const int c = n0 + wn + ni * 8 + 2 * tg;
            float2 v01 = make_float2(acc[mi][ni][0], acc[mi][ni][1]);
            float2 v23 = make_float2(acc[mi][ni][2], acc[mi][ni][3]);
            if (EPI & 1) {
                float2 bv = *(const float2*)(bias + c);
                v01.x += bv.x; v01.y += bv.y;
                v23.x += bv.x; v23.y += bv.y;
            }
            if (EPI & 4) {
                v01.x = gelu_exact(v01.x); v01.y = gelu_exact(v01.y);
                v23.x = gelu_exact(v23.x); v23.y = gelu_exact(v23.y);
            }
            size_t off0 = (size_t)r0 * ldc + c;
            size_t off1 = (size_t)(r0 + 8) * ldc + c;
            if (EPI & 2) {
                float2 q0 = *(const float2*)(res + off0);
                float2 q1 = *(const float2*)(res + off1);
                v01.x += q0.x; v01.y += q0.y;
                v23.x += q1.x; v23.y += q1.y;
            }
            if (EPI & 8) {
                v01.x = tf32r(v01.x); v01.y = tf32r(v01.y);
                v23.x = tf32r(v23.x); v23.y = tf32r(v23.y);
            }
            *(float2*)(C + off0) = v01;
            *(float2*)(C + off1) = v23;
        }
    }
}

// ---------------------------------------------------------------------------
// Sequential MPS recurrence. One WARP per (b,h) chain, 64 CTAs x 32 threads.
// M layout is j-major: M[bs][j*32+i] so lane j reads a contiguous 128B row.
// Padded smem rows (36 floats) -> LDS.128 at the 4-phase wavefront floor.
// h broadcast via smem; tanh.approx on the serial path; no block barriers.
// ---------------------------------------------------------------------------
__global__ void __launch_bounds__(32, 1) recurrence_kernel(
    const float* __restrict__ Mg, float* __restrict__ hs)
{
    __shared__ __align__(16) float sm[2][32][36];
    __shared__ __align__(16) float hsm[32];
    const int j = threadIdx.x;
    const int b = blockIdx.x >> 4;
    const int h = blockIdx.x & 15;
    const float* Mbh = Mg + ((size_t)h * BSROWS + (size_t)b * SEQ) * 1024;
    const uint32_t sbase = smem_u32(&sm[0][0][0]);
    const uint32_t rowoff = (uint32_t)j * 144;

    // preload s=0 into buf 0
    {
        const float* src = Mbh + j * 32;
#pragma unroll
        for (int c = 0; c < 8; c++) cp16(sbase + rowoff + c * 16, src + c * 4);
        asm volatile("cp.async.commit_group;");
    }
    hsm[j] = 0.17677669529663688f;   // 1/sqrt(32)
    asm volatile("cp.async.wait_group 0;");
    __syncwarp();

    float* hsb = hs + ((size_t)b * SEQ) * 512 + h * 32 + j;

    for (int s = 0; s < SEQ; ++s) {
        const int buf = s & 1;
        if (s + 1 < SEQ) {
            const float* src = Mbh + (size_t)(s + 1) * 1024 + j * 32;
            const uint32_t dst = sbase + (uint32_t)(buf ^ 1) * 4608 + rowoff;
#pragma unroll
            for (int c = 0; c < 8; c++) cp16(dst + c * 16, src + c * 4);
        }
        asm volatile("cp.async.commit_group;");

        const float* row = &sm[buf][j][0];
        float a0 = 0.f, a1 = 0.f, a2 = 0.f, a3 = 0.f;
#pragma unroll
        for (int c = 0; c < 8; c++) {
            float4 hv = *(const float4*)&hsm[c * 4];
            float4 rv = *(const float4*)&row[c * 4];
            a0 = fmaf(hv.x, rv.x, a0);
            a1 = fmaf(hv.y, rv.y, a1);
            a2 = fmaf(hv.z, rv.z, a2);
            a3 = fmaf(hv.w, rv.w, a3);
        }
        float r = tanh_fast((a0 + a1) + (a2 + a3));
        hsb[(size_t)s * 512] = tf32r(r);
        __syncwarp();          // all lanes done reading hsm
        hsm[j] = r;
        asm volatile("cp.async.wait_group 0;");
        __syncwarp();          // hsm write + next tile visible
    }
}

// ---------------------------------------------------------------------------
// Launch  (order puts gemm_x2 at launch #6 = the ncu -s 5 capture slot)
// ---------------------------------------------------------------------------
extern "C" void kernel_launch(void* const* d_in, const int* in_sizes, int n_in,
                              void* d_out, int out_size)
{
    const float* x     = (const float*)d_in[0];
    const float* ln1_g = (const float*)d_in[1];
    const float* ln1_b = (const float*)d_in[2];
    const float* W_in  = (const float*)d_in[3];
    const float* b_in  = (const float*)d_in[4];
    const float* A     = (const float*)d_in[5];
    const float* W_out = (const float*)d_in[6];
    const float* b_out = (const float*)d_in[7];
    const float* ln2_g = (const float*)d_in[8];
    const float* ln2_b = (const float*)d_in[9];
    const float* W1    = (const float*)d_in[10];
    const float* b1    = (const float*)d_in[11];
    const float* W2    = (const float*)d_in[12];
    const float* b2    = (const float*)d_in[13];
    float* out = (float*)d_out;

    float *ln, *v, *a2, *M, *hsp, *x2, *ffn, *winc, *woutc, *w1c, *w2c;
    cudaGetSymbolAddress((void**)&ln,    g_ln);
    cudaGetSymbolAddress((void**)&v,     g_v);
    cudaGetSymbolAddress((void**)&a2,    g_a2);
    cudaGetSymbolAddress((void**)&M,     g_M);
    cudaGetSymbolAddress((void**)&hsp,   g_hs);
    cudaGetSymbolAddress((void**)&x2,    g_x2);
    cudaGetSymbolAddress((void**)&ffn,   g_ffn);
    cudaGetSymbolAddress((void**)&winc,  g_winc);
    cudaGetSymbolAddress((void**)&woutc, g_woutc);
    cudaGetSymbolAddress((void**)&w1c,   g_w1c);
    cudaGetSymbolAddress((void**)&w2c,   g_w2c);

    // 1) merged prep (A2 rearrange + 4 weight tf32 copies)
    prep_kernel<<<13824, 256>>>(A, a2, W_in, winc, W_out, woutc, W1, w1c, W2, w2c);

    // 2) LN1
    ln_kernel<<<BSROWS, 256>>>(x, ln1_g, ln1_b, ln);

    // 3) v = ln @ W_in + b_in   [8192 x 1024 x 1024], tf32-rounded out
    tc_gemm<9><<<dim3(8, 64, 1), 256>>>(
        ln, winc, v, b_in, nullptr, DIM, DIM, DIM, DIM, 0, 0, 0);

    // 4) M[h] = v[:, h*64:(h+1)*64] @ A2[h]   16 heads, [8192 x 1024 x 64]
    tc_gemm<0><<<dim3(8, 64, NH), 256>>>(
        v, a2, M, nullptr, nullptr, 64, DIM, 1024, 1024,
        (size_t)64, (size_t)65536, (size_t)BSROWS * 1024);

    // 5) sequential recurrence -> hs (tf32-rounded)
    recurrence_kernel<<<64, 32>>>(M, hsp);

    // 6) x2 = x + hs @ W_out + b_out   [8192 x 1024 x 512]   <-- ncu capture
    tc_gemm<3><<<dim3(8, 64, 1), 256>>>(
        hsp, woutc, x2, b_out, x, 512, 512, DIM, DIM, 0, 0, 0);

    // 7) LN2
    ln_kernel<<<BSROWS, 256>>>(x2, ln2_g, ln2_b, ln);

    // 8) ffn = gelu(ln @ W1 + b1)  [8192 x 4096 x 1024], tf32-rounded out
    tc_gemm<13><<<dim3(32, 64, 1), 256>>>(
        ln, w1c, ffn, b1, nullptr, DIM, DIM, DFF, DFF, 0, 0, 0);

    // 9) out = x2 + ffn @ W2 + b2  [8192 x 1024 x 4096]
    tc_gemm<3><<<dim3(8, 64, 1), 256>>>(
        ffn, w2c, out, b2, x2, DFF, DFF, DIM, DIM, 0, 0, 0);
}

// round 6
// speedup vs baseline: 2.7678x; 1.3009x over previous
#include <cuda_runtime.h>
#include <math.h>
#include <cstdint>

#define BSROWS 8192
#define SEQ    2048
#define DIM    1024
#define NH     16
#define DFF    4096

// ---------------------------------------------------------------------------
// Scratch (device globals)
// ---------------------------------------------------------------------------
__device__ float g_ln   [8388608];    // LN output (tf32-rounded)
__device__ float g_v    [8388608];    // v = LN1(x)@W_in + b_in (tf32-rounded)
__device__ float g_a2   [1048576];    // A rearranged [h][p][j*32+i] (tf32)
__device__ float g_M    [134217728];  // M[h][bs][j*32+i] fp32
__device__ float g_hs   [4194304];    // recurrence out [bs][H*DH] (tf32)
__device__ float g_x2   [8388608];    // x + hs@W_out + b_out (fp32)
__device__ float g_ffn  [33554432];   // GELU(LN2@W1+b1) (tf32-rounded)
__device__ float g_winc [1048576];    // tf32(W_in)  [1024][1024]
__device__ float g_woutc[524288];     // tf32(W_out) [512][1024]
__device__ float g_w1c  [4194304];    // tf32(W1)    [1024][4096]
__device__ float g_w2c  [4194304];    // tf32(W2)    [4096][1024]

// ---------------------------------------------------------------------------
// Helpers
// ---------------------------------------------------------------------------
__device__ __forceinline__ uint32_t smem_u32(const void* p) {
    return (uint32_t)__cvta_generic_to_shared(p);
}
__device__ __forceinline__ float gelu_exact(float x) {
    return 0.5f * x * (1.0f + erff(x * 0.70710678118654752f));
}
__device__ __forceinline__ void cp16(uint32_t dst, const void* src) {
    asm volatile("cp.async.cg.shared.global [%0], [%1], 16;" :: "r"(dst), "l"(src));
}
__device__ __forceinline__ float tf32r(float x) {
    uint32_t t;
    asm("cvt.rna.tf32.f32 %0, %1;" : "=r"(t) : "f"(x));
    return __uint_as_float(t);
}
__device__ __forceinline__ float tanh_fast(float x) {
    float r;
    asm("tanh.approx.f32 %0, %1;" : "=f"(r) : "f"(x));
    return r;
}
__device__ __forceinline__ void mma_tf32(float* d, const float* a, const float* b) {
    asm volatile(
        "mma.sync.aligned.m16n8k8.row.col.f32.tf32.tf32.f32 "
        "{%0,%1,%2,%3}, {%4,%5,%6,%7}, {%8,%9}, {%0,%1,%2,%3};"
        : "+f"(d[0]), "+f"(d[1]), "+f"(d[2]), "+f"(d[3])
        : "r"(__float_as_uint(a[0])), "r"(__float_as_uint(a[1])),
          "r"(__float_as_uint(a[2])), "r"(__float_as_uint(a[3])),
          "r"(__float_as_uint(b[0])), "r"(__float_as_uint(b[1])));
}

// ---------------------------------------------------------------------------
// Merged prep: A rearrange + 4 weight tf32 copies.
//   idx < 1048576 : A[h][i][p][j] -> A2[h][p][j*32+i] (tf32)
// ---------------------------------------------------------------------------
__global__ void prep_kernel(const float* __restrict__ A, float* __restrict__ A2,
                            const float* __restrict__ Wi, float* __restrict__ Wic,
                            const float* __restrict__ Wo, float* __restrict__ Woc,
                            const float* __restrict__ W1, float* __restrict__ W1c,
                            const float* __restrict__ W2, float* __restrict__ W2c)
{
    int idx = blockIdx.x * 256 + threadIdx.x;
    if (idx < 1048576) {
        int j = idx & 31;
        int p = (idx >> 5) & 63;
        int i = (idx >> 11) & 31;
        int h = idx >> 16;
        A2[((h * 64 + p) << 10) + (j << 5) + i] = tf32r(A[idx]);
        return;
    }
    int t = idx - 1048576;
    const float* src; float* dst;
    if (t < 262144)            { src = Wi; dst = Wic; }
    else if ((t -= 262144) < 131072)  { src = Wo; dst = Woc; }
    else if ((t -= 131072) < 1048576) { src = W1; dst = W1c; }
    else if ((t -= 1048576) < 1048576){ src = W2; dst = W2c; }
    else return;
    float4 v = ((const float4*)src)[t];
    v.x = tf32r(v.x); v.y = tf32r(v.y); v.z = tf32r(v.z); v.w = tf32r(v.w);
    ((float4*)dst)[t] = v;
}

// ---------------------------------------------------------------------------
// LayerNorm over last dim (1024), output tf32-rounded.
// ---------------------------------------------------------------------------
__global__ void ln_kernel(const float* __restrict__ x, const float* __restrict__ g,
                          const float* __restrict__ b, float* __restrict__ y) {
    int row = blockIdx.x;
    int tid = threadIdx.x;
    const float* xr = x + (size_t)row * DIM;
    float v[4];
    float s = 0.f, sq = 0.f;
#pragma unroll
    for (int i = 0; i < 4; i++) {
        v[i] = xr[tid + i * 256];
        s  += v[i];
        sq += v[i] * v[i];
    }
#pragma unroll
    for (int o = 16; o > 0; o >>= 1) {
        s  += __shfl_xor_sync(0xffffffffu, s,  o);
        sq += __shfl_xor_sync(0xffffffffu, sq, o);
    }
    __shared__ float ss[8], sqq[8];
    int w = tid >> 5, l = tid & 31;
    if (l == 0) { ss[w] = s; sqq[w] = sq; }
    __syncthreads();
    if (w == 0) {
        s  = (l < 8) ? ss[l]  : 0.f;
        sq = (l < 8) ? sqq[l] : 0.f;
#pragma unroll
        for (int o = 4; o > 0; o >>= 1) {
            s  += __shfl_xor_sync(0xffffffffu, s,  o);
            sq += __shfl_xor_sync(0xffffffffu, sq, o);
        }
        if (l == 0) { ss[0] = s; sqq[0] = sq; }
    }
    __syncthreads();
    s = ss[0]; sq = sqq[0];
    float mean = s * (1.0f / DIM);
    float var  = sq * (1.0f / DIM) - mean * mean;
    float rstd = rsqrtf(var + 1e-5f);
    float* yr = y + (size_t)row * DIM;
#pragma unroll
    for (int i = 0; i < 4; i++) {
        int c = tid + i * 256;
        yr[c] = tf32r((v[i] - mean) * rstd * g[c] + b[c]);
    }
}

// ---------------------------------------------------------------------------
// tf32 warp-MMA GEMM: C[M,N] = A[M,K] @ B[K,N]
// CTA 128x128, BK=32, 3-stage cp.async pipeline (dynamic smem, 105KB),
// 8 warps (64x32 each), mma.sync.m16n8k8.
// SMEM: As [3][128][36] floats, Bs [3][32][136] floats (conflict-free frags).
// EPI: bit0=bias, bit1=residual, bit2=gelu, bit3=tf32-round output.
// Requires M%128==0, N%128==0, K%32==0 and K>=64.
// ---------------------------------------------------------------------------
#define GSMEM_BYTES 107520
template <int EPI>
__global__ void __launch_bounds__(256) tc_gemm(
    const float* __restrict__ A, const float* __restrict__ B, float* __restrict__ C,
    const float* __restrict__ bias, const float* __restrict__ res,
    int K, int lda, int ldb, int ldc,
    size_t batchA, size_t batchB, size_t batchC)
{
    extern __shared__ float smem[];
    float* As = smem;            // [3][128][36]
    float* Bs = smem + 13824;    // [3][32][136]

    A += (size_t)blockIdx.z * batchA;
    B += (size_t)blockIdx.z * batchB;
    C += (size_t)blockIdx.z * batchC;

    const int tid = threadIdx.x;
    const int m0 = blockIdx.y * 128, n0 = blockIdx.x * 128;
    const int wid = tid >> 5, lane = tid & 31;
    const int wm = (wid >> 2) * 64;
    const int wn = (wid & 3) * 32;
    const int gq = lane >> 2, tg = lane & 3;

    const uint32_t sA = smem_u32(As);
    const uint32_t sB = smem_u32(Bs);

    const int arow = tid >> 1, ahalf = tid & 1;   // A: 128 rows x 32 k, 2 thr/row
    const int brow = tid >> 3, bseg = tid & 7;    // B: 32 rows x 128 n, 8 thr/row

    auto loadA = [&](int st, int k0) {
        const float* src = A + (size_t)(m0 + arow) * lda + k0 + ahalf * 16;
        uint32_t dst = sA + ((uint32_t)st * 4608 + (uint32_t)arow * 36 + (uint32_t)ahalf * 16) * 4;
        cp16(dst, src); cp16(dst + 16, src + 4);
        cp16(dst + 32, src + 8); cp16(dst + 48, src + 12);
    };
    auto loadB = [&](int st, int k0) {
        const float* src = B + (size_t)(k0 + brow) * ldb + n0 + bseg * 16;
        uint32_t dst = sB + ((uint32_t)st * 4352 + (uint32_t)brow * 136 + (uint32_t)bseg * 16) * 4;
        cp16(dst, src); cp16(dst + 16, src + 4);
        cp16(dst + 32, src + 8); cp16(dst + 48, src + 12);
    };

    float acc[4][4][4];
#pragma unroll
    for (int mi = 0; mi < 4; mi++)
#pragma unroll
        for (int ni = 0; ni < 4; ni++)
#pragma unroll
            for (int q = 0; q < 4; q++) acc[mi][ni][q] = 0.f;

    const int KT = K >> 5;
    loadA(0, 0);  loadB(0, 0);
    asm volatile("cp.async.commit_group;");
    loadA(1, 32); loadB(1, 32);
    asm volatile("cp.async.commit_group;");

    for (int kt = 0; kt < KT; ++kt) {
        const int buf = kt % 3;
        asm volatile("cp.async.wait_group 1;");
        __syncthreads();
        if (kt + 2 < KT) {
            const int st = (kt + 2) % 3;
            loadA(st, (kt + 2) * 32);
            loadB(st, (kt + 2) * 32);
        }
        asm volatile("cp.async.commit_group;");

        const float* Ab = As + buf * 4608;
        const float* Bb = Bs + buf * 4352;
#pragma unroll
        for (int kk = 0; kk < 32; kk += 8) {
            float a[4][4], b[4][2];
#pragma unroll
            for (int mi = 0; mi < 4; mi++) {
                const int m = wm + mi * 16 + gq;
                a[mi][0] = Ab[m * 36 + kk + tg];
                a[mi][1] = Ab[(m + 8) * 36 + kk + tg];
                a[mi][2] = Ab[m * 36 + kk + tg + 4];
                a[mi][3] = Ab[(m + 8) * 36 + kk + tg + 4];
            }
#pragma unroll
            for (int ni = 0; ni < 4; ni++) {
                const int n = wn + ni * 8 + gq;
                b[ni][0] = Bb[(kk + tg) * 136 + n];
                b[ni][1] = Bb[(kk + tg + 4) * 136 + n];
            }
#pragma unroll
            for (int mi = 0; mi < 4; mi++)
#pragma unroll
                for (int ni = 0; ni < 4; ni++)
                    mma_tf32(acc[mi][ni], a[mi], b[ni]);
        }
    }

    // epilogue
#pragma unroll
    for (int mi = 0; mi < 4; mi++) {
        const int r0 = m0 + wm + mi * 16 + gq;
#pragma unroll
        for (int ni = 0; ni < 4; ni++) {
            const int c = n0 + wn + ni * 8 + 2 * tg;
            float2 v01 = make_float2(acc[mi][ni][0], acc[mi][ni][1]);
            float2 v23 = make_float2(acc[mi][ni][2], acc[mi][ni][3]);
            if (EPI & 1) {
                float2 bv = *(const float2*)(bias + c);
                v01.x += bv.x; v01.y += bv.y;
                v23.x += bv.x; v23.y += bv.y;
            }
            if (EPI & 4) {
                v01.x = gelu_exact(v01.x); v01.y = gelu_exact(v01.y);
                v23.x = gelu_exact(v23.x); v23.y = gelu_exact(v23.y);
            }
            size_t off0 = (size_t)r0 * ldc + c;
            size_t off1 = (size_t)(r0 + 8) * ldc + c;
            if (EPI & 2) {
                float2 q0 = *(const float2*)(res + off0);
                float2 q1 = *(const float2*)(res + off1);
                v01.x += q0.x; v01.y += q0.y;
                v23.x += q1.x; v23.y += q1.y;
            }
            if (EPI & 8) {
                v01.x = tf32r(v01.x); v01.y = tf32r(v01.y);
                v23.x = tf32r(v23.x); v23.y = tf32r(v23.y);
            }
            *(float2*)(C + off0) = v01;
            *(float2*)(C + off1) = v23;
        }
    }
}

// ---------------------------------------------------------------------------
// Sequential MPS recurrence. One WARP per (b,h) chain, 64 CTAs x 32 threads.
// 8-stage cp.async prefetch (distance 7) hides DRAM latency across steps.
// Lane j owns row j of each tile (no cross-lane tile dependency); only the
// h-vector crosses lanes, double-buffered in smem -> 1 syncwarp per step.
// Packed f32x2 FMA halves the serial FMA chain.
// ---------------------------------------------------------------------------
__global__ void __launch_bounds__(32, 1) recurrence_kernel(
    const float* __restrict__ Mg, float* __restrict__ hs)
{
    __shared__ __align__(16) float sm[8][32][36];
    __shared__ __align__(16) float hsm[2][32];
    const int j = threadIdx.x;
    const int b = blockIdx.x >> 4;
    const int h = blockIdx.x & 15;
    const float* Mbh = Mg + ((size_t)h * BSROWS + (size_t)b * SEQ) * 1024;
    const uint32_t sbase = smem_u32(&sm[0][0][0]) + (uint32_t)j * 144;

    // preload tiles 0..6 into stages 0..6, one group each
#pragma unroll
    for (int t = 0; t < 7; t++) {
        const float* src = Mbh + (size_t)t * 1024 + j * 32;
        const uint32_t dst = sbase + (uint32_t)t * 4608;
#pragma unroll
        for (int c = 0; c < 8; c++) cp16(dst + c * 16, src + c * 4);
        asm volatile("cp.async.commit_group;");
    }
    hsm[0][j] = 0.17677669529663688f;   // 1/sqrt(32)
    __syncwarp();

    float* hsb = hs + ((size_t)b * SEQ) * 512 + h * 32 + j;

    for (int s = 0; s < SEQ; ++s) {
        if (s + 7 < SEQ) {
            const float* src = Mbh + (size_t)(s + 7) * 1024 + j * 32;
            const uint32_t dst = sbase + (uint32_t)((s + 7) & 7) * 4608;
#pragma unroll
            for (int c = 0; c < 8; c++) cp16(dst + c * 16, src + c * 4);
        }
        asm volatile("cp.async.commit_group;");
        asm volatile("cp.async.wait_group 7;");   // tile s (this lane's row) ready

        const float* row = &sm[s & 7][j][0];
        const float* hv  = hsm[s & 1];
        unsigned long long accA = 0ull, accB = 0ull;
#pragma unroll
        for (int c = 0; c < 8; c++) {
            ulonglong2 h2 = *(const ulonglong2*)(hv + c * 4);
            ulonglong2 r2 = *(const ulonglong2*)(row + c * 4);
            asm("fma.rn.f32x2 %0, %1, %2, %0;" : "+l"(accA) : "l"(h2.x), "l"(r2.x));
            asm("fma.rn.f32x2 %0, %1, %2, %0;" : "+l"(accB) : "l"(h2.y), "l"(r2.y));
        }
        float2 fa = *(float2*)&accA;
        float2 fb = *(float2*)&accB;
        float r = tanh_fast((fa.x + fa.y) + (fb.x + fb.y));
        hsm[(s + 1) & 1][j] = r;
        hsb[(size_t)s * 512] = tf32r(r);
        __syncwarp();   // h write visible before next step's reads
    }
}

// ---------------------------------------------------------------------------
// Launch  (gemm_x2 stays at launch #6 = the ncu -s 5 capture slot)
// ---------------------------------------------------------------------------
extern "C" void kernel_launch(void* const* d_in, const int* in_sizes, int n_in,
                              void* d_out, int out_size)
{
    const float* x     = (const float*)d_in[0];
    const float* ln1_g = (const float*)d_in[1];
    const float* ln1_b = (const float*)d_in[2];
    const float* W_in  = (const float*)d_in[3];
    const float* b_in  = (const float*)d_in[4];
    const float* A     = (const float*)d_in[5];
    const float* W_out = (const float*)d_in[6];
    const float* b_out = (const float*)d_in[7];
    const float* ln2_g = (const float*)d_in[8];
    const float* ln2_b = (const float*)d_in[9];
    const float* W1    = (const float*)d_in[10];
    const float* b1    = (const float*)d_in[11];
    const float* W2    = (const float*)d_in[12];
    const float* b2    = (const float*)d_in[13];
    float* out = (float*)d_out;

    float *ln, *v, *a2, *M, *hsp, *x2, *ffn, *winc, *woutc, *w1c, *w2c;
    cudaGetSymbolAddress((void**)&ln,    g_ln);
    cudaGetSymbolAddress((void**)&v,     g_v);
    cudaGetSymbolAddress((void**)&a2,    g_a2);
    cudaGetSymbolAddress((void**)&M,     g_M);
    cudaGetSymbolAddress((void**)&hsp,   g_hs);
    cudaGetSymbolAddress((void**)&x2,    g_x2);
    cudaGetSymbolAddress((void**)&ffn,   g_ffn);
    cudaGetSymbolAddress((void**)&winc,  g_winc);
    cudaGetSymbolAddress((void**)&woutc, g_woutc);
    cudaGetSymbolAddress((void**)&w1c,   g_w1c);
    cudaGetSymbolAddress((void**)&w2c,   g_w2c);

    cudaFuncSetAttribute((const void*)tc_gemm<0>,  cudaFuncAttributeMaxDynamicSharedMemorySize, GSMEM_BYTES);
    cudaFuncSetAttribute((const void*)tc_gemm<3>,  cudaFuncAttributeMaxDynamicSharedMemorySize, GSMEM_BYTES);
    cudaFuncSetAttribute((const void*)tc_gemm<9>,  cudaFuncAttributeMaxDynamicSharedMemorySize, GSMEM_BYTES);
    cudaFuncSetAttribute((const void*)tc_gemm<13>, cudaFuncAttributeMaxDynamicSharedMemorySize, GSMEM_BYTES);

    // 1) merged prep
    prep_kernel<<<13824, 256>>>(A, a2, W_in, winc, W_out, woutc, W1, w1c, W2, w2c);

    // 2) LN1
    ln_kernel<<<BSROWS, 256>>>(x, ln1_g, ln1_b, ln);

    // 3) v = ln @ W_in + b_in   [8192 x 1024 x 1024], tf32-rounded out
    tc_gemm<9><<<dim3(8, 64, 1), 256, GSMEM_BYTES>>>(
        ln, winc, v, b_in, nullptr, DIM, DIM, DIM, DIM, 0, 0, 0);

    // 4) M[h] = v[:, h*64:(h+1)*64] @ A2[h]   16 heads, [8192 x 1024 x 64]
    tc_gemm<0><<<dim3(8, 64, NH), 256, GSMEM_BYTES>>>(
        v, a2, M, nullptr, nullptr, 64, DIM, 1024, 1024,
        (size_t)64, (size_t)65536, (size_t)BSROWS * 1024);

    // 5) sequential recurrence -> hs (tf32-rounded)
    recurrence_kernel<<<64, 32>>>(M, hsp);

    // 6) x2 = x + hs @ W_out + b_out   [8192 x 1024 x 512]   <-- ncu capture
    tc_gemm<3><<<dim3(8, 64, 1), 256, GSMEM_BYTES>>>(
        hsp, woutc, x2, b_out, x, 512, 512, DIM, DIM, 0, 0, 0);

    // 7) LN2
    ln_kernel<<<BSROWS, 256>>>(x2, ln2_g, ln2_b, ln);

    // 8) ffn = gelu(ln @ W1 + b1)  [8192 x 4096 x 1024], tf32-rounded out
    tc_gemm<13><<<dim3(32, 64, 1), 256, GSMEM_BYTES>>>(
        ln, w1c, ffn, b1, nullptr, DIM, DIM, DFF, DFF, 0, 0, 0);

    // 9) out = x2 + ffn @ W2 + b2  [8192 x 1024 x 4096]
    tc_gemm<3><<<dim3(8, 64, 1), 256, GSMEM_BYTES>>>(
        ffn, w2c, out, b2, x2, DFF, DFF, DIM, DIM, 0, 0, 0);
}

// round 7
// speedup vs baseline: 2.7757x; 1.0028x over previous
#include <cuda_runtime.h>
#include <math.h>
#include <cstdint>

#define BSROWS 8192
#define SEQ    2048
#define DIM    1024
#define NH     16
#define DFF    4096

// ---------------------------------------------------------------------------
// Scratch (device globals)
// ---------------------------------------------------------------------------
__device__ float g_ln   [8388608];    // LN output (tf32-rounded)
__device__ float g_v    [8388608];    // v = LN1(x)@W_in + b_in (tf32-rounded)
__device__ float g_a2   [1048576];    // A rearranged [h][p][j*32+i] (tf32)
__device__ float g_M    [134217728];  // M[h][bs][j*32+i] fp32
__device__ float g_hs   [4194304];    // recurrence out [bs][H*DH] (tf32)
__device__ float g_x2   [8388608];    // x + hs@W_out + b_out (fp32)
__device__ float g_ffn  [33554432];   // GELU(LN2@W1+b1) (tf32-rounded)
__device__ float g_winc [1048576];    // tf32(W_in)  [1024][1024]
__device__ float g_woutc[524288];     // tf32(W_out) [512][1024]
__device__ float g_w1c  [4194304];    // tf32(W1)    [1024][4096]
__device__ float g_w2c  [4194304];    // tf32(W2)    [4096][1024]

// ---------------------------------------------------------------------------
// Helpers
// ---------------------------------------------------------------------------
__device__ __forceinline__ uint32_t smem_u32(const void* p) {
    return (uint32_t)__cvta_generic_to_shared(p);
}
__device__ __forceinline__ float gelu_exact(float x) {
    return 0.5f * x * (1.0f + erff(x * 0.70710678118654752f));
}
__device__ __forceinline__ void cp16(uint32_t dst, const void* src) {
    asm volatile("cp.async.cg.shared.global [%0], [%1], 16;" :: "r"(dst), "l"(src));
}
__device__ __forceinline__ float tf32r(float x) {
    uint32_t t;
    asm("cvt.rna.tf32.f32 %0, %1;" : "=r"(t) : "f"(x));
    return __uint_as_float(t);
}
__device__ __forceinline__ float tanh_fast(float x) {
    float r;
    asm("tanh.approx.f32 %0, %1;" : "=f"(r) : "f"(x));
    return r;
}
__device__ __forceinline__ void mma_tf32(float* d, const float* a, const float* b) {
    asm volatile(
        "mma.sync.aligned.m16n8k8.row.col.f32.tf32.tf32.f32 "
        "{%0,%1,%2,%3}, {%4,%5,%6,%7}, {%8,%9}, {%0,%1,%2,%3};"
        : "+f"(d[0]), "+f"(d[1]), "+f"(d[2]), "+f"(d[3])
        : "r"(__float_as_uint(a[0])), "r"(__float_as_uint(a[1])),
          "r"(__float_as_uint(a[2])), "r"(__float_as_uint(a[3])),
          "r"(__float_as_uint(b[0])), "r"(__float_as_uint(b[1])));
}

// ---------------------------------------------------------------------------
// Merged prep: A rearrange + 4 weight tf32 copies.
// ---------------------------------------------------------------------------
__global__ void prep_kernel(const float* __restrict__ A, float* __restrict__ A2,
                            const float* __restrict__ Wi, float* __restrict__ Wic,
                            const float* __restrict__ Wo, float* __restrict__ Woc,
                            const float* __restrict__ W1, float* __restrict__ W1c,
                            const float* __restrict__ W2, float* __restrict__ W2c)
{
    int idx = blockIdx.x * 256 + threadIdx.x;
    if (idx < 1048576) {
        int j = idx & 31;
        int p = (idx >> 5) & 63;
        int i = (idx >> 11) & 31;
        int h = idx >> 16;
        A2[((h * 64 + p) << 10) + (j << 5) + i] = tf32r(A[idx]);
        return;
    }
    int t = idx - 1048576;
    const float* src; float* dst;
    if (t < 262144)            { src = Wi; dst = Wic; }
    else if ((t -= 262144) < 131072)  { src = Wo; dst = Woc; }
    else if ((t -= 131072) < 1048576) { src = W1; dst = W1c; }
    else if ((t -= 1048576) < 1048576){ src = W2; dst = W2c; }
    else return;
    float4 v = ((const float4*)src)[t];
    v.x = tf32r(v.x); v.y = tf32r(v.y); v.z = tf32r(v.z); v.w = tf32r(v.w);
    ((float4*)dst)[t] = v;
}

// ---------------------------------------------------------------------------
// LayerNorm over last dim (1024), output tf32-rounded.
// ---------------------------------------------------------------------------
__global__ void ln_kernel(const float* __restrict__ x, const float* __restrict__ g,
                          const float* __restrict__ b, float* __restrict__ y) {
    int row = blockIdx.x;
    int tid = threadIdx.x;
    const float* xr = x + (size_t)row * DIM;
    float v[4];
    float s = 0.f, sq = 0.f;
#pragma unroll
    for (int i = 0; i < 4; i++) {
        v[i] = xr[tid + i * 256];
        s  += v[i];
        sq += v[i] * v[i];
    }
#pragma unroll
    for (int o = 16; o > 0; o >>= 1) {
        s  += __shfl_xor_sync(0xffffffffu, s,  o);
        sq += __shfl_xor_sync(0xffffffffu, sq, o);
    }
    __shared__ float ss[8], sqq[8];
    int w = tid >> 5, l = tid & 31;
    if (l == 0) { ss[w] = s; sqq[w] = sq; }
    __syncthreads();
    if (w == 0) {
        s  = (l < 8) ? ss[l]  : 0.f;
        sq = (l < 8) ? sqq[l] : 0.f;
#pragma unroll
        for (int o = 4; o > 0; o >>= 1) {
            s  += __shfl_xor_sync(0xffffffffu, s,  o);
            sq += __shfl_xor_sync(0xffffffffu, sq, o);
        }
        if (l == 0) { ss[0] = s; sqq[0] = sq; }
    }
    __syncthreads();
    s = ss[0]; sq = sqq[0];
    float mean = s * (1.0f / DIM);
    float var  = sq * (1.0f / DIM) - mean * mean;
    float rstd = rsqrtf(var + 1e-5f);
    float* yr = y + (size_t)row * DIM;
#pragma unroll
    for (int i = 0; i < 4; i++) {
        int c = tid + i * 256;
        yr[c] = tf32r((v[i] - mean) * rstd * g[c] + b[c]);
    }
}

// ---------------------------------------------------------------------------
// tf32 warp-MMA GEMM: C[M,N] = A[M,K] @ B[K,N]
// CTA 128x128, BK=32, 3-stage cp.async smem pipeline + REGISTER-level
// double-buffered fragments (load group g+1 while issuing group g MMAs).
// 8 warps (64x32 each), mma.sync.m16n8k8.
// EPI: bit0=bias, bit1=residual, bit2=gelu, bit3=tf32-round output.
// ---------------------------------------------------------------------------
#define GSMEM_BYTES 107520

__device__ __forceinline__ void ldfrag(
    const float* __restrict__ Ab, const float* __restrict__ Bb, int kk,
    int wm, int wn, int gq, int tg, float a[4][4], float b[4][2])
{
#pragma unroll
    for (int mi = 0; mi < 4; mi++) {
        const int m = wm + mi * 16 + gq;
        a[mi][0] = Ab[m * 36 + kk + tg];
        a[mi][1] = Ab[(m + 8) * 36 + kk + tg];
        a[mi][2] = Ab[m * 36 + kk + tg + 4];
        a[mi][3] = Ab[(m + 8) * 36 + kk + tg + 4];
    }
#pragma unroll
    for (int ni = 0; ni < 4; ni++) {
        const int n = wn + ni * 8 + gq;
        b[ni][0] = Bb[(kk + tg) * 136 + n];
        b[ni][1] = Bb[(kk + tg + 4) * 136 + n];
    }
}

template <int EPI>
__global__ void __launch_bounds__(256, 2) tc_gemm(
    const float* __restrict__ A, const float* __restrict__ B, float* __restrict__ C,
    const float* __restrict__ bias, const float* __restrict__ res,
    int K, int lda, int ldb, int ldc,
    size_t batchA, size_t batchB, size_t batchC)
{
    extern __shared__ float smem[];
    float* As = smem;            // [3][128][36]
    float* Bs = smem + 13824;    // [3][32][136]

    A += (size_t)blockIdx.z * batchA;
    B += (size_t)blockIdx.z * batchB;
    C += (size_t)blockIdx.z * batchC;

    const int tid = threadIdx.x;
    const int m0 = blockIdx.y * 128, n0 = blockIdx.x * 128;
    const int wid = tid >> 5, lane = tid & 31;
    const int wm = (wid >> 2) * 64;
    const int wn = (wid & 3) * 32;
    const int gq = lane >> 2, tg = lane & 3;

    const uint32_t sA = smem_u32(As);
    const uint32_t sB = smem_u32(Bs);

    const int arow = tid >> 1, ahalf = tid & 1;
    const int brow = tid >> 3, bseg = tid & 7;

    auto loadA = [&](int st, int k0) {
        const float* src = A + (size_t)(m0 + arow) * lda + k0 + ahalf * 16;
        uint32_t dst = sA + ((uint32_t)st * 4608 + (uint32_t)arow * 36 + (uint32_t)ahalf * 16) * 4;
        cp16(dst, src); cp16(dst + 16, src + 4);
        cp16(dst + 32, src + 8); cp16(dst + 48, src + 12);
    };
    auto loadB = [&](int st, int k0) {
        const float* src = B + (size_t)(k0 + brow) * ldb + n0 + bseg * 16;
        uint32_t dst = sB + ((uint32_t)st * 4352 + (uint32_t)brow * 136 + (uint32_t)bseg * 16) * 4;
        cp16(dst, src); cp16(dst + 16, src + 4);
        cp16(dst + 32, src + 8); cp16(dst + 48, src + 12);
    };

    float acc[4][4][4];
#pragma unroll
    for (int mi = 0; mi < 4; mi++)
#pragma unroll
        for (int ni = 0; ni < 4; ni++)
#pragma unroll
            for (int q = 0; q < 4; q++) acc[mi][ni][q] = 0.f;

    const int KT = K >> 5;
    loadA(0, 0);  loadB(0, 0);
    asm volatile("cp.async.commit_group;");
    loadA(1, 32); loadB(1, 32);
    asm volatile("cp.async.commit_group;");

    for (int kt = 0; kt < KT; ++kt) {
        const int buf = kt % 3;
        asm volatile("cp.async.wait_group 1;");
        __syncthreads();
        if (kt + 2 < KT) {
            const int st = (kt + 2) % 3;
            loadA(st, (kt + 2) * 32);
            loadB(st, (kt + 2) * 32);
        }
        asm volatile("cp.async.commit_group;");

        const float* Ab = As + buf * 4608;
        const float* Bb = Bs + buf * 4352;

        // register double-buffered fragment pipeline over 4 k8-groups
        float aF[2][4][4], bF[2][4][2];
        ldfrag(Ab, Bb, 0, wm, wn, gq, tg, aF[0], bF[0]);
#pragma unroll
        for (int g = 0; g < 4; g++) {
            if (g < 3)
                ldfrag(Ab, Bb, (g + 1) * 8, wm, wn, gq, tg,
                       aF[(g + 1) & 1], bF[(g + 1) & 1]);
#pragma unroll
            for (int mi = 0; mi < 4; mi++)
#pragma unroll
                for (int ni = 0; ni < 4; ni++)
                    mma_tf32(acc[mi][ni], aF[g & 1][mi], bF[g & 1][ni]);
        }
    }

    // epilogue
#pragma unroll
    for (int mi = 0; mi < 4; mi++) {
        const int r0 = m0 + wm + mi * 16 + gq;
#pragma unroll
        for (int ni = 0; ni < 4; ni++) {
            const int c = n0 + wn + ni * 8 + 2 * tg;
            float2 v01 = make_float2(acc[mi][ni][0], acc[mi][ni][1]);
            float2 v23 = make_float2(acc[mi][ni][2], acc[mi][ni][3]);
            if (EPI & 1) {
                float2 bv = *(const float2*)(bias + c);
                v01.x += bv.x; v01.y += bv.y;
                v23.x += bv.x; v23.y += bv.y;
            }
            if (EPI & 4) {
                v01.x = gelu_exact(v01.x); v01.y = gelu_exact(v01.y);
                v23.x = gelu_exact(v23.x); v23.y = gelu_exact(v23.y);
            }
            size_t off0 = (size_t)r0 * ldc + c;
            size_t off1 = (size_t)(r0 + 8) * ldc + c;
            if (EPI & 2) {
                float2 q0 = *(const float2*)(res + off0);
                float2 q1 = *(const float2*)(res + off1);
                v01.x += q0.x; v01.y += q0.y;
                v23.x += q1.x; v23.y += q1.y;
            }
            if (EPI & 8) {
                v01.x = tf32r(v01.x); v01.y = tf32r(v01.y);
                v23.x = tf32r(v23.x); v23.y = tf32r(v23.y);
            }
            *(float2*)(C + off0) = v01;
            *(float2*)(C + off1) = v23;
        }
    }
}

// ---------------------------------------------------------------------------
// Sequential MPS recurrence (unchanged from R6 — it delivered).
// ---------------------------------------------------------------------------
__global__ void __launch_bounds__(32, 1) recurrence_kernel(
    const float* __restrict__ Mg, float* __restrict__ hs)
{
    __shared__ __align__(16) float sm[8][32][36];
    __shared__ __align__(16) float hsm[2][32];
    const int j = threadIdx.x;
    const int b = blockIdx.x >> 4;
    const int h = blockIdx.x & 15;
    const float* Mbh = Mg + ((size_t)h * BSROWS + (size_t)b * SEQ) * 1024;
    const uint32_t sbase = smem_u32(&sm[0][0][0]) + (uint32_t)j * 144;

#pragma unroll
    for (int t = 0; t < 7; t++) {
        const float* src = Mbh + (size_t)t * 1024 + j * 32;
        const uint32_t dst = sbase + (uint32_t)t * 4608;
#pragma unroll
        for (int c = 0; c < 8; c++) cp16(dst + c * 16, src + c * 4);
        asm volatile("cp.async.commit_group;");
    }
    hsm[0][j] = 0.17677669529663688f;   // 1/sqrt(32)
    __syncwarp();

    float* hsb = hs + ((size_t)b * SEQ) * 512 + h * 32 + j;

    for (int s = 0; s < SEQ; ++s) {
        if (s + 7 < SEQ) {
            const float* src = Mbh + (size_t)(s + 7) * 1024 + j * 32;
            const uint32_t dst = sbase + (uint32_t)((s + 7) & 7) * 4608;
#pragma unroll
            for (int c = 0; c < 8; c++) cp16(dst + c * 16, src + c * 4);
        }
        asm volatile("cp.async.commit_group;");
        asm volatile("cp.async.wait_group 7;");

        const float* row = &sm[s & 7][j][0];
        const float* hv  = hsm[s & 1];
        unsigned long long accA = 0ull, accB = 0ull;
#pragma unroll
        for (int c = 0; c < 8; c++) {
            ulonglong2 h2 = *(const ulonglong2*)(hv + c * 4);
            ulonglong2 r2 = *(const ulonglong2*)(row + c * 4);
            asm("fma.rn.f32x2 %0, %1, %2, %0;" : "+l"(accA) : "l"(h2.x), "l"(r2.x));
            asm("fma.rn.f32x2 %0, %1, %2, %0;" : "+l"(accB) : "l"(h2.y), "l"(r2.y));
        }
        float2 fa = *(float2*)&accA;
        float2 fb = *(float2*)&accB;
        float r = tanh_fast((fa.x + fa.y) + (fb.x + fb.y));
        hsm[(s + 1) & 1][j] = r;
        hsb[(size_t)s * 512] = tf32r(r);
        __syncwarp();
    }
}

// ---------------------------------------------------------------------------
// Launch  (gemm_x2 stays at launch #6 = the ncu -s 5 capture slot)
// ---------------------------------------------------------------------------
extern "C" void kernel_launch(void* const* d_in, const int* in_sizes, int n_in,
                              void* d_out, int out_size)
{
    const float* x     = (const float*)d_in[0];
    const float* ln1_g = (const float*)d_in[1];
    const float* ln1_b = (const float*)d_in[2];
    const float* W_in  = (const float*)d_in[3];
    const float* b_in  = (const float*)d_in[4];
    const float* A     = (const float*)d_in[5];
    const float* W_out = (const float*)d_in[6];
    const float* b_out = (const float*)d_in[7];
    const float* ln2_g = (const float*)d_in[8];
    const float* ln2_b = (const float*)d_in[9];
    const float* W1    = (const float*)d_in[10];
    const float* b1    = (const float*)d_in[11];
    const float* W2    = (const float*)d_in[12];
    const float* b2    = (const float*)d_in[13];
    float* out = (float*)d_out;

    float *ln, *v, *a2, *M, *hsp, *x2, *ffn, *winc, *woutc, *w1c, *w2c;
    cudaGetSymbolAddress((void**)&ln,    g_ln);
    cudaGetSymbolAddress((void**)&v,     g_v);
    cudaGetSymbolAddress((void**)&a2,    g_a2);
    cudaGetSymbolAddress((void**)&M,     g_M);
    cudaGetSymbolAddress((void**)&hsp,   g_hs);
    cudaGetSymbolAddress((void**)&x2,    g_x2);
    cudaGetSymbolAddress((void**)&ffn,   g_ffn);
    cudaGetSymbolAddress((void**)&winc,  g_winc);
    cudaGetSymbolAddress((void**)&woutc, g_woutc);
    cudaGetSymbolAddress((void**)&w1c,   g_w1c);
    cudaGetSymbolAddress((void**)&w2c,   g_w2c);

    cudaFuncSetAttribute((const void*)tc_gemm<0>,  cudaFuncAttributeMaxDynamicSharedMemorySize, GSMEM_BYTES);
    cudaFuncSetAttribute((const void*)tc_gemm<3>,  cudaFuncAttributeMaxDynamicSharedMemorySize, GSMEM_BYTES);
    cudaFuncSetAttribute((const void*)tc_gemm<9>,  cudaFuncAttributeMaxDynamicSharedMemorySize, GSMEM_BYTES);
    cudaFuncSetAttribute((const void*)tc_gemm<13>, cudaFuncAttributeMaxDynamicSharedMemorySize, GSMEM_BYTES);

    // 1) merged prep
    prep_kernel<<<13824, 256>>>(A, a2, W_in, winc, W_out, woutc, W1, w1c, W2, w2c);

    // 2) LN1
    ln_kernel<<<BSROWS, 256>>>(x, ln1_g, ln1_b, ln);

    // 3) v = ln @ W_in + b_in   [8192 x 1024 x 1024], tf32-rounded out
    tc_gemm<9><<<dim3(8, 64, 1), 256, GSMEM_BYTES>>>(
        ln, winc, v, b_in, nullptr, DIM, DIM, DIM, DIM, 0, 0, 0);

    // 4) M[h] = v[:, h*64:(h+1)*64] @ A2[h]   16 heads, [8192 x 1024 x 64]
    tc_gemm<0><<<dim3(8, 64, NH), 256, GSMEM_BYTES>>>(
        v, a2, M, nullptr, nullptr, 64, DIM, 1024, 1024,
        (size_t)64, (size_t)65536, (size_t)BSROWS * 1024);

    // 5) sequential recurrence -> hs (tf32-rounded)
    recurrence_kernel<<<64, 32>>>(M, hsp);

    // 6) x2 = x + hs @ W_out + b_out   [8192 x 1024 x 512]   <-- ncu capture
    tc_gemm<3><<<dim3(8, 64, 1), 256, GSMEM_BYTES>>>(
        hsp, woutc, x2, b_out, x, 512, 512, DIM, DIM, 0, 0, 0);

    // 7) LN2
    ln_kernel<<<BSROWS, 256>>>(x2, ln2_g, ln2_b, ln);

    // 8) ffn = gelu(ln @ W1 + b1)  [8192 x 4096 x 1024], tf32-rounded out
    tc_gemm<13><<<dim3(32, 64, 1), 256, GSMEM_BYTES>>>(
        ln, w1c, ffn, b1, nullptr, DIM, DIM, DFF, DFF, 0, 0, 0);

    // 9) out = x2 + ffn @ W2 + b2  [8192 x 1024 x 4096]
    tc_gemm<3><<<dim3(8, 64, 1), 256, GSMEM_BYTES>>>(
        ffn, w2c, out, b2, x2, DFF, DFF, DIM, DIM, 0, 0, 0);
}

// round 8
// speedup vs baseline: 4.0666x; 1.4651x over previous
#include <cuda_runtime.h>
#include <cuda_fp16.h>
#include <math.h>
#include <cstdint>

#define BSROWS 8192
#define SEQ    2048
#define DIM    1024
#define NH     16
#define DFF    4096

// ---------------------------------------------------------------------------
// Scratch (device globals)
// ---------------------------------------------------------------------------
__device__ float  g_ln   [8388608];    // LN1 output (tf32-rounded)
__device__ __half g_lnh  [8388608];    // LN2 output (fp16)
__device__ float  g_v    [8388608];    // v = LN1(x)@W_in + b_in (tf32-rounded)
__device__ float  g_a2   [1048576];    // A rearranged [h][p][j*32+i] (tf32)
__device__ float  g_M    [134217728];  // M[h][bs][j*32+i] fp32
__device__ float  g_hs   [4194304];    // recurrence out [bs][H*DH] (tf32)
__device__ float  g_x2   [8388608];    // x + hs@W_out + b_out (fp32)
__device__ __half g_ffnh [33554432];   // GELU(LN2@W1+b1) (fp16)
__device__ float  g_winc [1048576];    // tf32(W_in)  [1024][1024]
__device__ float  g_woutc[524288];     // tf32(W_out) [512][1024]
__device__ __half g_w1h  [4194304];    // fp16(W1^T)  [4096][1024]
__device__ __half g_w2h  [4194304];    // fp16(W2^T)  [1024][4096]

// ---------------------------------------------------------------------------
// Helpers
// ---------------------------------------------------------------------------
__device__ __forceinline__ uint32_t smem_u32(const void* p) {
    return (uint32_t)__cvta_generic_to_shared(p);
}
__device__ __forceinline__ float gelu_exact(float x) {
    return 0.5f * x * (1.0f + erff(x * 0.70710678118654752f));
}
__device__ __forceinline__ void cp16(uint32_t dst, const void* src) {
    asm volatile("cp.async.cg.shared.global [%0], [%1], 16;" :: "r"(dst), "l"(src));
}
__device__ __forceinline__ float tf32r(float x) {
    uint32_t t;
    asm("cvt.rna.tf32.f32 %0, %1;" : "=r"(t) : "f"(x));
    return __uint_as_float(t);
}
__device__ __forceinline__ float tanh_fast(float x) {
    float r;
    asm("tanh.approx.f32 %0, %1;" : "=f"(r) : "f"(x));
    return r;
}
__device__ __forceinline__ void mma_tf32(float* d, const float* a, const float* b) {
    asm volatile(
        "mma.sync.aligned.m16n8k8.row.col.f32.tf32.tf32.f32 "
        "{%0,%1,%2,%3}, {%4,%5,%6,%7}, {%8,%9}, {%0,%1,%2,%3};"
        : "+f"(d[0]), "+f"(d[1]), "+f"(d[2]), "+f"(d[3])
        : "r"(__float_as_uint(a[0])), "r"(__float_as_uint(a[1])),
          "r"(__float_as_uint(a[2])), "r"(__float_as_uint(a[3])),
          "r"(__float_as_uint(b[0])), "r"(__float_as_uint(b[1])));
}
__device__ __forceinline__ void mma_f16(float* d, const uint32_t* a, const uint32_t* b) {
    asm volatile(
        "mma.sync.aligned.m16n8k16.row.col.f32.f16.f16.f32 "
        "{%0,%1,%2,%3}, {%4,%5,%6,%7}, {%8,%9}, {%0,%1,%2,%3};"
        : "+f"(d[0]), "+f"(d[1]), "+f"(d[2]), "+f"(d[3])
        : "r"(a[0]), "r"(a[1]), "r"(a[2]), "r"(a[3]),
          "r"(b[0]), "r"(b[1]));
}

// ---------------------------------------------------------------------------
// Merged prep: A rearrange + W_in/W_out tf32 copies.
// ---------------------------------------------------------------------------
__global__ void prep_kernel(const float* __restrict__ A, float* __restrict__ A2,
                            const float* __restrict__ Wi, float* __restrict__ Wic,
                            const float* __restrict__ Wo, float* __restrict__ Woc)
{
    int idx = blockIdx.x * 256 + threadIdx.x;
    if (idx < 1048576) {
        int j = idx & 31;
        int p = (idx >> 5) & 63;
        int i = (idx >> 11) & 31;
        int h = idx >> 16;
        A2[((h * 64 + p) << 10) + (j << 5) + i] = tf32r(A[idx]);
        return;
    }
    int t = idx - 1048576;
    const float* src; float* dst;
    if (t < 262144)                  { src = Wi; dst = Wic; }
    else if ((t -= 262144) < 131072) { src = Wo; dst = Woc; }
    else return;
    float4 v = ((const float4*)src)[t];
    v.x = tf32r(v.x); v.y = tf32r(v.y); v.z = tf32r(v.z); v.w = tf32r(v.w);
    ((float4*)dst)[t] = v;
}

// ---------------------------------------------------------------------------
// Transpose + fp16 convert: in[R][C] fp32 -> out[C][R] fp16.
// ---------------------------------------------------------------------------
__global__ void tconv_kernel(const float* __restrict__ in, __half* __restrict__ out,
                             int R, int C) {
    __shared__ float t[32][33];
    int bx = blockIdx.x * 32, by = blockIdx.y * 32;
    int tx = threadIdx.x, ty = threadIdx.y;
#pragma unroll
    for (int j = 0; j < 32; j += 8)
        t[ty + j][tx] = in[(size_t)(by + ty + j) * C + bx + tx];
    __syncthreads();
#pragma unroll
    for (int j = 0; j < 32; j += 8)
        out[(size_t)(bx + ty + j) * R + by + tx] = __float2half(t[tx][ty + j]);
}

// ---------------------------------------------------------------------------
// LayerNorm (fp32 in, tf32-rounded fp32 out) — used for LN1.
// ---------------------------------------------------------------------------
__global__ void ln_kernel(const float* __restrict__ x, const float* __restrict__ g,
                          const float* __restrict__ b, float* __restrict__ y) {
    int row = blockIdx.x;
    int tid = threadIdx.x;
    const float* xr = x + (size_t)row * DIM;
    float v[4];
    float s = 0.f, sq = 0.f;
#pragma unroll
    for (int i = 0; i < 4; i++) {
        v[i] = xr[tid + i * 256];
        s  += v[i];
        sq += v[i] * v[i];
    }
#pragma unroll
    for (int o = 16; o > 0; o >>= 1) {
        s  += __shfl_xor_sync(0xffffffffu, s,  o);
        sq += __shfl_xor_sync(0xffffffffu, sq, o);
    }
    __shared__ float ss[8], sqq[8];
    int w = tid >> 5, l = tid & 31;
    if (l == 0) { ss[w] = s; sqq[w] = sq; }
    __syncthreads();
    if (w == 0) {
        s  = (l < 8) ? ss[l]  : 0.f;
        sq = (l < 8) ? sqq[l] : 0.f;
#pragma unroll
        for (int o = 4; o > 0; o >>= 1) {
            s  += __shfl_xor_sync(0xffffffffu, s,  o);
            sq += __shfl_xor_sync(0xffffffffu, sq, o);
        }
        if (l == 0) { ss[0] = s; sqq[0] = sq; }
    }
    __syncthreads();
    s = ss[0]; sq = sqq[0];
    float mean = s * (1.0f / DIM);
    float var  = sq * (1.0f / DIM) - mean * mean;
    float rstd = rsqrtf(var + 1e-5f);
    float* yr = y + (size_t)row * DIM;
#pragma unroll
    for (int i = 0; i < 4; i++) {
        int c = tid + i * 256;
        yr[c] = tf32r((v[i] - mean) * rstd * g[c] + b[c]);
    }
}

// ---------------------------------------------------------------------------
// LayerNorm writing fp16 — used for LN2 (feeds fp16 FFN GEMM).
// ---------------------------------------------------------------------------
__global__ void ln_h_kernel(const float* __restrict__ x, const float* __restrict__ g,
                            const float* __restrict__ b, __half* __restrict__ y) {
    int row = blockIdx.x;
    int tid = threadIdx.x;
    const float* xr = x + (size_t)row * DIM;
    float v[4];
    float s = 0.f, sq = 0.f;
#pragma unroll
    for (int i = 0; i < 4; i++) {
        v[i] = xr[tid + i * 256];
        s  += v[i];
        sq += v[i] * v[i];
    }
#pragma unroll
    for (int o = 16; o > 0; o >>= 1) {
        s  += __shfl_xor_sync(0xffffffffu, s,  o);
        sq += __shfl_xor_sync(0xffffffffu, sq, o);
    }
    __shared__ float ss[8], sqq[8];
    int w = tid >> 5, l = tid & 31;
    if (l == 0) { ss[w] = s; sqq[w] = sq; }
    __syncthreads();
    if (w == 0) {
        s  = (l < 8) ? ss[l]  : 0.f;
        sq = (l < 8) ? sqq[l] : 0.f;
#pragma unroll
        for (int o = 4; o > 0; o >>= 1) {
            s  += __shfl_xor_sync(0xffffffffu, s,  o);
            sq += __shfl_xor_sync(0xffffffffu, sq, o);
        }
        if (l == 0) { ss[0] = s; sqq[0] = sq; }
    }
    __syncthreads();
    s = ss[0]; sq = sqq[0];
    float mean = s * (1.0f / DIM);
    float var  = sq * (1.0f / DIM) - mean * mean;
    float rstd = rsqrtf(var + 1e-5f);
    __half* yr = y + (size_t)row * DIM;
#pragma unroll
    for (int i = 0; i < 4; i++) {
        int c = tid + i * 256;
        yr[c] = __float2half((v[i] - mean) * rstd * g[c] + b[c]);
    }
}

// ---------------------------------------------------------------------------
// tf32 warp-MMA GEMM (R7 version, unchanged): C[M,N] = A[M,K] @ B[K,N].
// ---------------------------------------------------------------------------
#define GSMEM_BYTES 107520

__device__ __forceinline__ void ldfrag(
    const float* __restrict__ Ab, const float* __restrict__ Bb, int kk,
    int wm, int wn, int gq, int tg, float a[4][4], float b[4][2])
{
#pragma unroll
    for (int mi = 0; mi < 4; mi++) {
        const int m = wm + mi * 16 + gq;
        a[mi][0] = Ab[m * 36 + kk + tg];
        a[mi][1] = Ab[(m + 8) * 36 + kk + tg];
        a[mi][2] = Ab[m * 36 + kk + tg + 4];
        a[mi][3] = Ab[(m + 8) * 36 + kk + tg + 4];
    }
#pragma unroll
    for (int ni = 0; ni < 4; ni++) {
        const int n = wn + ni * 8 + gq;
        b[ni][0] = Bb[(kk + tg) * 136 + n];
        b[ni][1] = Bb[(kk + tg + 4) * 136 + n];
    }
}

template <int EPI>
__global__ void __launch_bounds__(256, 2) tc_gemm(
    const float* __restrict__ A, const float* __restrict__ B, float* __restrict__ C,
    const float* __restrict__ bias, const float* __restrict__ res,
    int K, int lda, int ldb, int ldc,
    size_t batchA, size_t batchB, size_t batchC)
{
    extern __shared__ float smem[];
    float* As = smem;            // [3][128][36]
    float* Bs = smem + 13824;    // [3][32][136]

    A += (size_t)blockIdx.z * batchA;
    B += (size_t)blockIdx.z * batchB;
    C += (size_t)blockIdx.z * batchC;

    const int tid = threadIdx.x;
    const int m0 = blockIdx.y * 128, n0 = blockIdx.x * 128;
    const int wid = tid >> 5, lane = tid & 31;
    const int wm = (wid >> 2) * 64;
    const int wn = (wid & 3) * 32;
    const int gq = lane >> 2, tg = lane & 3;

    const uint32_t sA = smem_u32(As);
    const uint32_t sB = smem_u32(Bs);

    const int arow = tid >> 1, ahalf = tid & 1;
    const int brow = tid >> 3, bseg = tid & 7;

    auto loadA = [&](int st, int k0) {
        const float* src = A + (size_t)(m0 + arow) * lda + k0 + ahalf * 16;
        uint32_t dst = sA + ((uint32_t)st * 4608 + (uint32_t)arow * 36 + (uint32_t)ahalf * 16) * 4;
        cp16(dst, src); cp16(dst + 16, src + 4);
        cp16(dst + 32, src + 8); cp16(dst + 48, src + 12);
    };
    auto loadB = [&](int st, int k0) {
        const float* src = B + (size_t)(k0 + brow) * ldb + n0 + bseg * 16;
        uint32_t dst = sB + ((uint32_t)st * 4352 + (uint32_t)brow * 136 + (uint32_t)bseg * 16) * 4;
        cp16(dst, src); cp16(dst + 16, src + 4);
        cp16(dst + 32, src + 8); cp16(dst + 48, src + 12);
    };

    float acc[4][4][4];
#pragma unroll
    for (int mi = 0; mi < 4; mi++)
#pragma unroll
        for (int ni = 0; ni < 4; ni++)
#pragma unroll
            for (int q = 0; q < 4; q++) acc[mi][ni][q] = 0.f;

    const int KT = K >> 5;
    loadA(0, 0);  loadB(0, 0);
    asm volatile("cp.async.commit_group;");
    loadA(1, 32); loadB(1, 32);
    asm volatile("cp.async.commit_group;");

    for (int kt = 0; kt < KT; ++kt) {
        const int buf = kt % 3;
        asm volatile("cp.async.wait_group 1;");
        __syncthreads();
        if (kt + 2 < KT) {
            const int st = (kt + 2) % 3;
            loadA(st, (kt + 2) * 32);
            loadB(st, (kt + 2) * 32);
        }
        asm volatile("cp.async.commit_group;");

        const float* Ab = As + buf * 4608;
        const float* Bb = Bs + buf * 4352;

        float aF[2][4][4], bF[2][4][2];
        ldfrag(Ab, Bb, 0, wm, wn, gq, tg, aF[0], bF[0]);
#pragma unroll
        for (int g = 0; g < 4; g++) {
            if (g < 3)
                ldfrag(Ab, Bb, (g + 1) * 8, wm, wn, gq, tg,
                       aF[(g + 1) & 1], bF[(g + 1) & 1]);
#pragma unroll
            for (int mi = 0; mi < 4; mi++)
#pragma unroll
                for (int ni = 0; ni < 4; ni++)
                    mma_tf32(acc[mi][ni], aF[g & 1][mi], bF[g & 1][ni]);
        }
    }

#pragma unroll
    for (int mi = 0; mi < 4; mi++) {
        const int r0 = m0 + wm + mi * 16 + gq;
#pragma unroll
        for (int ni = 0; ni < 4; ni++) {
            const int c = n0 + wn + ni * 8 + 2 * tg;
            float2 v01 = make_float2(acc[mi][ni][0], acc[mi][ni][1]);
            float2 v23 = make_float2(acc[mi][ni][2], acc[mi][ni][3]);
            if (EPI & 1) {
                float2 bv = *(const float2*)(bias + c);
                v01.x += bv.x; v01.y += bv.y;
                v23.x += bv.x; v23.y += bv.y;
            }
            size_t off0 = (size_t)r0 * ldc + c;
            size_t off1 = (size_t)(r0 + 8) * ldc + c;
            if (EPI & 2) {
                float2 q0 = *(const float2*)(res + off0);
                float2 q1 = *(const float2*)(res + off1);
                v01.x += q0.x; v01.y += q0.y;
                v23.x += q1.x; v23.y += q1.y;
            }
            if (EPI & 8) {
                v01.x = tf32r(v01.x); v01.y = tf32r(v01.y);
                v23.x = tf32r(v23.x); v23.y = tf32r(v23.y);
            }
            *(float2*)(C + off0) = v01;
            *(float2*)(C + off1) = v23;
        }
    }
}

// ---------------------------------------------------------------------------
// fp16 warp-MMA GEMM: C[M,N] = A[M,K] @ BT[N,K]^T
// A row-major fp16 [M][K]; BT row-major fp16 [N][K] (pre-transposed weights).
// CTA 128x128, BK=32, 3-stage cp.async, 8 warps (64x32), mma.m16n8k16.
// SMEM: As [3][128][40] halves, Bs [3][128][40] halves (conflict-free).
// EPI: bit0=bias, bit1=residual(float), bit2=gelu.  OT: __half or float.
// ---------------------------------------------------------------------------
#define HSMEM_BYTES 61440

template <int EPI, typename OT>
__global__ void __launch_bounds__(256, 2) hgemm(
    const __half* __restrict__ A, const __half* __restrict__ BT, OT* __restrict__ C,
    const float* __restrict__ bias, const float* __restrict__ res,
    int K, int lda, int ldb, int ldc)
{
    extern __shared__ __half hsm[];
    __half* As = hsm;            // [3][128][40]
    __half* Bs = hsm + 15360;    // [3][128][40]

    const int tid = threadIdx.x;
    const int m0 = blockIdx.y * 128, n0 = blockIdx.x * 128;
    const int wid = tid >> 5, lane = tid & 31;
    const int wm = (wid >> 2) * 64;
    const int wn = (wid & 3) * 32;
    const int gq = lane >> 2, tg = lane & 3;

    const uint32_t sA = smem_u32(As);
    const uint32_t sB = smem_u32(Bs);

    const int row = tid >> 1, half = tid & 1;   // 2 threads per 64B row

    auto loadA = [&](int st, int k0) {
        const __half* src = A + (size_t)(m0 + row) * lda + k0 + half * 16;
        uint32_t dst = sA + (uint32_t)st * 10240 + (uint32_t)row * 80 + (uint32_t)half * 32;
        cp16(dst, src); cp16(dst + 16, src + 8);
    };
    auto loadB = [&](int st, int k0) {
        const __half* src = BT + (size_t)(n0 + row) * ldb + k0 + half * 16;
        uint32_t dst = sB + (uint32_t)st * 10240 + (uint32_t)row * 80 + (uint32_t)half * 32;
        cp16(dst, src); cp16(dst + 16, src + 8);
    };

    float acc[4][4][4];
#pragma unroll
    for (int mi = 0; mi < 4; mi++)
#pragma unroll
        for (int ni = 0; ni < 4; ni++)
#pragma unroll
            for (int q = 0; q < 4; q++) acc[mi][ni][q] = 0.f;

    const int KT = K >> 5;
    loadA(0, 0);  loadB(0, 0);
    asm volatile("cp.async.commit_group;");
    loadA(1, 32); loadB(1, 32);
    asm volatile("cp.async.commit_group;");

    for (int kt = 0; kt < KT; ++kt) {
        const int buf = kt % 3;
        asm volatile("cp.async.wait_group 1;");
        __syncthreads();
        if (kt + 2 < KT) {
            const int st = (kt + 2) % 3;
            loadA(st, (kt + 2) * 32);
            loadB(st, (kt + 2) * 32);
        }
        asm volatile("cp.async.commit_group;");

        const __half* Ab = As + buf * 5120;
        const __half* Bb = Bs + buf * 5120;
#pragma unroll
        for (int kk = 0; kk < 32; kk += 16) {
            uint32_t a[4][4], b[4][2];
#pragma unroll
            for (int mi = 0; mi < 4; mi++) {
                const __half* p0 = Ab + (wm + mi * 16 + gq) * 40 + kk + 2 * tg;
                const __half* p1 = p0 + 8 * 40;
                a[mi][0] = *(const uint32_t*)p0;
                a[mi][1] = *(const uint32_t*)p1;
                a[mi][2] = *(const uint32_t*)(p0 + 8);
                a[mi][3] = *(const uint32_t*)(p1 + 8);
            }
#pragma unroll
            for (int ni = 0; ni < 4; ni++) {
                const __half* q = Bb + (wn + ni * 8 + gq) * 40 + kk + 2 * tg;
                b[ni][0] = *(const uint32_t*)q;
                b[ni][1] = *(const uint32_t*)(q + 8);
            }
#pragma unroll
            for (int mi = 0; mi < 4; mi++)
#pragma unroll
                for (int ni = 0; ni < 4; ni++)
                    mma_f16(acc[mi][ni], a[mi], b[ni]);
        }
    }

    // epilogue
#pragma unroll
    for (int mi = 0; mi < 4; mi++) {
        const int r0 = m0 + wm + mi * 16 + gq;
#pragma unroll
        for (int ni = 0; ni < 4; ni++) {
            const int c = n0 + wn + ni * 8 + 2 * tg;
            float2 v01 = make_float2(acc[mi][ni][0], acc[mi][ni][1]);
            float2 v23 = make_float2(acc[mi][ni][2], acc[mi][ni][3]);
            if (EPI & 1) {
                float2 bv = *(const float2*)(bias + c);
                v01.x += bv.x; v01.y += bv.y;
                v23.x += bv.x; v23.y += bv.y;
            }
            if (EPI & 4) {
                v01.x = gelu_exact(v01.x); v01.y = gelu_exact(v01.y);
                v23.x = gelu_exact(v23.x); v23.y = gelu_exact(v23.y);
            }
            size_t off0 = (size_t)r0 * ldc + c;
            size_t off1 = (size_t)(r0 + 8) * ldc + c;
            if (EPI & 2) {
                float2 q0 = *(const float2*)(res + off0);
                float2 q1 = *(const float2*)(res + off1);
                v01.x += q0.x; v01.y += q0.y;
                v23.x += q1.x; v23.y += q1.y;
            }
            if constexpr (sizeof(OT) == 2) {
                *(__half2*)((__half*)C + off0) = __floats2half2_rn(v01.x, v01.y);
                *(__half2*)((__half*)C + off1) = __floats2half2_rn(v23.x, v23.y);
            } else {
                *(float2*)((float*)C + off0) = v01;
                *(float2*)((float*)C + off1) = v23;
            }
        }
    }
}

// ---------------------------------------------------------------------------
// Sequential MPS recurrence (unchanged — R6 version).
// ---------------------------------------------------------------------------
__global__ void __launch_bounds__(32, 1) recurrence_kernel(
    const float* __restrict__ Mg, float* __restrict__ hs)
{
    __shared__ __align__(16) float sm[8][32][36];
    __shared__ __align__(16) float hsm[2][32];
    const int j = threadIdx.x;
    const int b = blockIdx.x >> 4;
    const int h = blockIdx.x & 15;
    const float* Mbh = Mg + ((size_t)h * BSROWS + (size_t)b * SEQ) * 1024;
    const uint32_t sbase = smem_u32(&sm[0][0][0]) + (uint32_t)j * 144;

#pragma unroll
    for (int t = 0; t < 7; t++) {
        const float* src = Mbh + (size_t)t * 1024 + j * 32;
        const uint32_t dst = sbase + (uint32_t)t * 4608;
#pragma unroll
        for (int c = 0; c < 8; c++) cp16(dst + c * 16, src + c * 4);
        asm volatile("cp.async.commit_group;");
    }
    hsm[0][j] = 0.17677669529663688f;   // 1/sqrt(32)
    __syncwarp();

    float* hsb = hs + ((size_t)b * SEQ) * 512 + h * 32 + j;

    for (int s = 0; s < SEQ; ++s) {
        if (s + 7 < SEQ) {
            const float* src = Mbh + (size_t)(s + 7) * 1024 + j * 32;
            const uint32_t dst = sbase + (uint32_t)((s + 7) & 7) * 4608;
#pragma unroll
            for (int c = 0; c < 8; c++) cp16(dst + c * 16, src + c * 4);
        }
        asm volatile("cp.async.commit_group;");
        asm volatile("cp.async.wait_group 7;");

        const float* row = &sm[s & 7][j][0];
        const float* hv  = hsm[s & 1];
        unsigned long long accA = 0ull, accB = 0ull;
#pragma unroll
        for (int c = 0; c < 8; c++) {
            ulonglong2 h2 = *(const ulonglong2*)(hv + c * 4);
            ulonglong2 r2 = *(const ulonglong2*)(row + c * 4);
            asm("fma.rn.f32x2 %0, %1, %2, %0;" : "+l"(accA) : "l"(h2.x), "l"(r2.x));
            asm("fma.rn.f32x2 %0, %1, %2, %0;" : "+l"(accB) : "l"(h2.y), "l"(r2.y));
        }
        float2 fa = *(float2*)&accA;
        float2 fb = *(float2*)&accB;
        float r = tanh_fast((fa.x + fa.y) + (fb.x + fb.y));
        hsm[(s + 1) & 1][j] = r;
        hsb[(size_t)s * 512] = tf32r(r);
        __syncwarp();
    }
}

// ---------------------------------------------------------------------------
// Launch
// ---------------------------------------------------------------------------
extern "C" void kernel_launch(void* const* d_in, const int* in_sizes, int n_in,
                              void* d_out, int out_size)
{
    const float* x     = (const float*)d_in[0];
    const float* ln1_g = (const float*)d_in[1];
    const float* ln1_b = (const float*)d_in[2];
    const float* W_in  = (const float*)d_in[3];
    const float* b_in  = (const float*)d_in[4];
    const float* A     = (const float*)d_in[5];
    const float* W_out = (const float*)d_in[6];
    const float* b_out = (const float*)d_in[7];
    const float* ln2_g = (const float*)d_in[8];
    const float* ln2_b = (const float*)d_in[9];
    const float* W1    = (const float*)d_in[10];
    const float* b1    = (const float*)d_in[11];
    const float* W2    = (const float*)d_in[12];
    const float* b2    = (const float*)d_in[13];
    float* out = (float*)d_out;

    float *ln, *v, *a2, *M, *hsp, *x2, *winc, *woutc;
    __half *lnh, *ffnh, *w1h, *w2h;
    cudaGetSymbolAddress((void**)&ln,    g_ln);
    cudaGetSymbolAddress((void**)&lnh,   g_lnh);
    cudaGetSymbolAddress((void**)&v,     g_v);
    cudaGetSymbolAddress((void**)&a2,    g_a2);
    cudaGetSymbolAddress((void**)&M,     g_M);
    cudaGetSymbolAddress((void**)&hsp,   g_hs);
    cudaGetSymbolAddress((void**)&x2,    g_x2);
    cudaGetSymbolAddress((void**)&ffnh,  g_ffnh);
    cudaGetSymbolAddress((void**)&winc,  g_winc);
    cudaGetSymbolAddress((void**)&woutc, g_woutc);
    cudaGetSymbolAddress((void**)&w1h,   g_w1h);
    cudaGetSymbolAddress((void**)&w2h,   g_w2h);

    cudaFuncSetAttribute((const void*)tc_gemm<0>, cudaFuncAttributeMaxDynamicSharedMemorySize, GSMEM_BYTES);
    cudaFuncSetAttribute((const void*)tc_gemm<3>, cudaFuncAttributeMaxDynamicSharedMemorySize, GSMEM_BYTES);
    cudaFuncSetAttribute((const void*)tc_gemm<9>, cudaFuncAttributeMaxDynamicSharedMemorySize, GSMEM_BYTES);
    cudaFuncSetAttribute((const void*)(hgemm<5, __half>), cudaFuncAttributeMaxDynamicSharedMemorySize, HSMEM_BYTES);
    cudaFuncSetAttribute((const void*)(hgemm<3, float>),  cudaFuncAttributeMaxDynamicSharedMemorySize, HSMEM_BYTES);

    // 1) prep (A2 rearrange + W_in/W_out tf32 copies)
    prep_kernel<<<5632, 256>>>(A, a2, W_in, winc, W_out, woutc);

    // 2-3) W1 [1024][4096] -> w1h [4096][1024] fp16; W2 [4096][1024] -> w2h [1024][4096]
    tconv_kernel<<<dim3(DFF / 32, DIM / 32), dim3(32, 8)>>>(W1, w1h, DIM, DFF);
    tconv_kernel<<<dim3(DIM / 32, DFF / 32), dim3(32, 8)>>>(W2, w2h, DFF, DIM);

    // 4) LN1
    ln_kernel<<<BSROWS, 256>>>(x, ln1_g, ln1_b, ln);

    // 5) v = ln @ W_in + b_in   [8192 x 1024 x 1024], tf32-rounded out
    tc_gemm<9><<<dim3(8, 64, 1), 256, GSMEM_BYTES>>>(
        ln, winc, v, b_in, nullptr, DIM, DIM, DIM, DIM, 0, 0, 0);

    // 6) M[h] = v[:, h*64:(h+1)*64] @ A2[h]   <-- ncu capture slot
    tc_gemm<0><<<dim3(8, 64, NH), 256, GSMEM_BYTES>>>(
        v, a2, M, nullptr, nullptr, 64, DIM, 1024, 1024,
        (size_t)64, (size_t)65536, (size_t)BSROWS * 1024);

    // 7) sequential recurrence -> hs
    recurrence_kernel<<<64, 32>>>(M, hsp);

    // 8) x2 = x + hs @ W_out + b_out   [8192 x 1024 x 512]
    tc_gemm<3><<<dim3(8, 64, 1), 256, GSMEM_BYTES>>>(
        hsp, woutc, x2, b_out, x, 512, 512, DIM, DIM, 0, 0, 0);

    // 9) LN2 -> fp16
    ln_h_kernel<<<BSROWS, 256>>>(x2, ln2_g, ln2_b, lnh);

    // 10) ffn = gelu(lnh @ W1 + b1)  fp16 in/out  [8192 x 4096 x 1024]
    hgemm<5, __half><<<dim3(32, 64, 1), 256, HSMEM_BYTES>>>(
        lnh, w1h, ffnh, b1, nullptr, DIM, DIM, DIM, DFF);

    // 11) out = x2 + ffnh @ W2 + b2  [8192 x 1024 x 4096]
    hgemm<3, float><<<dim3(8, 64, 1), 256, HSMEM_BYTES>>>(
        ffnh, w2h, out, b2, x2, DFF, DFF, DFF, DIM);
}

// round 9
// speedup vs baseline: 5.0673x; 1.2461x over previous
#include <cuda_runtime.h>
#include <cuda_fp16.h>
#include <math.h>
#include <cstdint>

#define BSROWS 8192
#define SEQ    2048
#define DIM    1024
#define NH     16
#define DFF    4096

// ---------------------------------------------------------------------------
// Scratch (device globals) — fp16 everywhere except the residual stream.
// ---------------------------------------------------------------------------
__device__ __half g_lnh  [8388608];    // LN output (reused LN1/LN2)
__device__ __half g_vh   [8388608];    // v = LN1@W_in + b_in
__device__ __half g_a2h  [1048576];    // A rearranged [h][j*32+i][p]
__device__ __half g_Mh   [134217728];  // M[h][bs][j*32+i]   (268MB)
__device__ __half g_hsh  [4194304];    // recurrence out [bs][H*DH]
__device__ float  g_x2   [8388608];    // x + hs@W_out + b_out (fp32 residual)
__device__ __half g_ffnh [33554432];   // GELU(LN2@W1+b1)
__device__ __half g_winh [1048576];    // W_in^T  [1024][1024]
__device__ __half g_wouth[524288];     // W_out^T [1024][512]
__device__ __half g_w1h  [4194304];    // W1^T    [4096][1024]
__device__ __half g_w2h  [4194304];    // W2^T    [1024][4096]

// ---------------------------------------------------------------------------
// Helpers
// ---------------------------------------------------------------------------
__device__ __forceinline__ uint32_t smem_u32(const void* p) {
    return (uint32_t)__cvta_generic_to_shared(p);
}
__device__ __forceinline__ float gelu_exact(float x) {
    return 0.5f * x * (1.0f + erff(x * 0.70710678118654752f));
}
__device__ __forceinline__ void cp16(uint32_t dst, const void* src) {
    asm volatile("cp.async.cg.shared.global [%0], [%1], 16;" :: "r"(dst), "l"(src));
}
__device__ __forceinline__ float tanh_fast(float x) {
    float r;
    asm("tanh.approx.f32 %0, %1;" : "=f"(r) : "f"(x));
    return r;
}
__device__ __forceinline__ void mma_f16(float* d, const uint32_t* a, const uint32_t* b) {
    asm volatile(
        "mma.sync.aligned.m16n8k16.row.col.f32.f16.f16.f32 "
        "{%0,%1,%2,%3}, {%4,%5,%6,%7}, {%8,%9}, {%0,%1,%2,%3};"
        : "+f"(d[0]), "+f"(d[1]), "+f"(d[2]), "+f"(d[3])
        : "r"(a[0]), "r"(a[1]), "r"(a[2]), "r"(a[3]),
          "r"(b[0]), "r"(b[1]));
}

// ---------------------------------------------------------------------------
// prep: A[h][i][p][j] -> a2h[h][j*32+i][p]  (fp16)   1,048,576 elements
// ---------------------------------------------------------------------------
__global__ void prep_A_kernel(const float* __restrict__ A, __half* __restrict__ A2) {
    int idx = blockIdx.x * 256 + threadIdx.x;
    int j = idx & 31;
    int p = (idx >> 5) & 63;
    int i = (idx >> 11) & 31;
    int h = idx >> 16;
    A2[(size_t)h * 65536 + (size_t)(j * 32 + i) * 64 + p] = __float2half(A[idx]);
}

// ---------------------------------------------------------------------------
// Merged weight transposes (fp32 [R][C] -> fp16 [C][R]) for W1,W2,W_in,W_out.
// One 32x32 tile per block, dispatched by flat blockIdx.x.
// ---------------------------------------------------------------------------
__device__ __forceinline__ void ttile(const float* __restrict__ in,
                                      __half* __restrict__ out,
                                      int R, int C, int bx, int by) {
    __shared__ float t[32][33];
    int tx = threadIdx.x, ty = threadIdx.y;
    int x0 = bx * 32, y0 = by * 32;
#pragma unroll
    for (int j = 0; j < 32; j += 8)
        t[ty + j][tx] = in[(size_t)(y0 + ty + j) * C + x0 + tx];
    __syncthreads();
#pragma unroll
    for (int j = 0; j < 32; j += 8)
        out[(size_t)(x0 + ty + j) * R + y0 + tx] = __float2half(t[tx][ty + j]);
}

__global__ void tconv_all_kernel(const float* __restrict__ W1, __half* __restrict__ w1h,
                                 const float* __restrict__ W2, __half* __restrict__ w2h,
                                 const float* __restrict__ Wi, __half* __restrict__ wih,
                                 const float* __restrict__ Wo, __half* __restrict__ woh)
{
    int t = blockIdx.x;
    if (t < 4096)        ttile(W1, w1h, 1024, 4096, t & 127, t >> 7);          // W1 [1024][4096]
    else if (t < 8192)   { t -= 4096; ttile(W2, w2h, 4096, 1024, t & 31, t >> 5); }
    else if (t < 9216)   { t -= 8192; ttile(Wi, wih, 1024, 1024, t & 31, t >> 5); }
    else                 { t -= 9216; ttile(Wo, woh, 512, 1024, t & 31, t >> 5); }
}

// ---------------------------------------------------------------------------
// LayerNorm (fp32 in, fp16 out).
// ---------------------------------------------------------------------------
__global__ void ln_h_kernel(const float* __restrict__ x, const float* __restrict__ g,
                            const float* __restrict__ b, __half* __restrict__ y) {
    int row = blockIdx.x;
    int tid = threadIdx.x;
    const float* xr = x + (size_t)row * DIM;
    float v[4];
    float s = 0.f, sq = 0.f;
#pragma unroll
    for (int i = 0; i < 4; i++) {
        v[i] = xr[tid + i * 256];
        s  += v[i];
        sq += v[i] * v[i];
    }
#pragma unroll
    for (int o = 16; o > 0; o >>= 1) {
        s  += __shfl_xor_sync(0xffffffffu, s,  o);
        sq += __shfl_xor_sync(0xffffffffu, sq, o);
    }
    __shared__ float ss[8], sqq[8];
    int w = tid >> 5, l = tid & 31;
    if (l == 0) { ss[w] = s; sqq[w] = sq; }
    __syncthreads();
    if (w == 0) {
        s  = (l < 8) ? ss[l]  : 0.f;
        sq = (l < 8) ? sqq[l] : 0.f;
#pragma unroll
        for (int o = 4; o > 0; o >>= 1) {
            s  += __shfl_xor_sync(0xffffffffu, s,  o);
            sq += __shfl_xor_sync(0xffffffffu, sq, o);
        }
        if (l == 0) { ss[0] = s; sqq[0] = sq; }
    }
    __syncthreads();
    s = ss[0]; sq = sqq[0];
    float mean = s * (1.0f / DIM);
    float var  = sq * (1.0f / DIM) - mean * mean;
    float rstd = rsqrtf(var + 1e-5f);
    __half* yr = y + (size_t)row * DIM;
#pragma unroll
    for (int i = 0; i < 4; i++) {
        int c = tid + i * 256;
        yr[c] = __float2half((v[i] - mean) * rstd * g[c] + b[c]);
    }
}

// ---------------------------------------------------------------------------
// fp16 warp-MMA GEMM: C[M,N] = A[M,K] @ BT[N,K]^T   (fp32 accumulate)
// A row-major fp16 [M][K]; BT row-major fp16 [N][K].
// CTA 128x128, BK=32, 3-stage cp.async, 8 warps (64x32), mma.m16n8k16.
// Batched via blockIdx.z (element strides).
// EPI: bit0=bias, bit1=residual(float), bit2=gelu.  OT: __half or float.
// ---------------------------------------------------------------------------
#define HSMEM_BYTES 61440

template <int EPI, typename OT>
__global__ void __launch_bounds__(256, 2) hgemm(
    const __half* __restrict__ A, const __half* __restrict__ BT, OT* __restrict__ C,
    const float* __restrict__ bias, const float* __restrict__ res,
    int K, int lda, int ldb, int ldc,
    size_t batchA, size_t batchB, size_t batchC)
{
    extern __shared__ __half hsm[];
    __half* As = hsm;            // [3][128][40]
    __half* Bs = hsm + 15360;    // [3][128][40]

    A  += (size_t)blockIdx.z * batchA;
    BT += (size_t)blockIdx.z * batchB;
    C  += (size_t)blockIdx.z * batchC;

    const int tid = threadIdx.x;
    const int m0 = blockIdx.y * 128, n0 = blockIdx.x * 128;
    const int wid = tid >> 5, lane = tid & 31;
    const int wm = (wid >> 2) * 64;
    const int wn = (wid & 3) * 32;
    const int gq = lane >> 2, tg = lane & 3;

    const uint32_t sA = smem_u32(As);
    const uint32_t sB = smem_u32(Bs);

    const int row = tid >> 1, half = tid & 1;   // 2 threads per 64B row

    auto loadA = [&](int st, int k0) {
        const __half* src = A + (size_t)(m0 + row) * lda + k0 + half * 16;
        uint32_t dst = sA + (uint32_t)st * 10240 + (uint32_t)row * 80 + (uint32_t)half * 32;
        cp16(dst, src); cp16(dst + 16, src + 8);
    };
    auto loadB = [&](int st, int k0) {
        const __half* src = BT + (size_t)(n0 + row) * ldb + k0 + half * 16;
        uint32_t dst = sB + (uint32_t)st * 10240 + (uint32_t)row * 80 + (uint32_t)half * 32;
        cp16(dst, src); cp16(dst + 16, src + 8);
    };

    float acc[4][4][4];
#pragma unroll
    for (int mi = 0; mi < 4; mi++)
#pragma unroll
        for (int ni = 0; ni < 4; ni++)
#pragma unroll
            for (int q = 0; q < 4; q++) acc[mi][ni][q] = 0.f;

    const int KT = K >> 5;
    loadA(0, 0);  loadB(0, 0);
    asm volatile("cp.async.commit_group;");
    loadA(1, 32); loadB(1, 32);
    asm volatile("cp.async.commit_group;");

    for (int kt = 0; kt < KT; ++kt) {
        const int buf = kt % 3;
        asm volatile("cp.async.wait_group 1;");
        __syncthreads();
        if (kt + 2 < KT) {
            const int st = (kt + 2) % 3;
            loadA(st, (kt + 2) * 32);
            loadB(st, (kt + 2) * 32);
        }
        asm volatile("cp.async.commit_group;");

        const __half* Ab = As + buf * 5120;
        const __half* Bb = Bs + buf * 5120;
#pragma unroll
        for (int kk = 0; kk < 32; kk += 16) {
            uint32_t a[4][4], b[4][2];
#pragma unroll
            for (int mi = 0; mi < 4; mi++) {
                const __half* p0 = Ab + (wm + mi * 16 + gq) * 40 + kk + 2 * tg;
                const __half* p1 = p0 + 8 * 40;
                a[mi][0] = *(const uint32_t*)p0;
                a[mi][1] = *(const uint32_t*)p1;
                a[mi][2] = *(const uint32_t*)(p0 + 8);
                a[mi][3] = *(const uint32_t*)(p1 + 8);
            }
#pragma unroll
            for (int ni = 0; ni < 4; ni++) {
                const __half* q = Bb + (wn + ni * 8 + gq) * 40 + kk + 2 * tg;
                b[ni][0] = *(const uint32_t*)q;
                b[ni][1] = *(const uint32_t*)(q + 8);
            }
#pragma unroll
            for (int mi = 0; mi < 4; mi++)
#pragma unroll
                for (int ni = 0; ni < 4; ni++)
                    mma_f16(acc[mi][ni], a[mi], b[ni]);
        }
    }

    // epilogue
#pragma unroll
    for (int mi = 0; mi < 4; mi++) {
        const int r0 = m0 + wm + mi * 16 + gq;
#pragma unroll
        for (int ni = 0; ni < 4; ni++) {
            const int c = n0 + wn + ni * 8 + 2 * tg;
            float2 v01 = make_float2(acc[mi][ni][0], acc[mi][ni][1]);
            float2 v23 = make_float2(acc[mi][ni][2], acc[mi][ni][3]);
            if (EPI & 1) {
                float2 bv = *(const float2*)(bias + c);
                v01.x += bv.x; v01.y += bv.y;
                v23.x += bv.x; v23.y += bv.y;
            }
            if (EPI & 4) {
                v01.x = gelu_exact(v01.x); v01.y = gelu_exact(v01.y);
                v23.x = gelu_exact(v23.x); v23.y = gelu_exact(v23.y);
            }
            size_t off0 = (size_t)r0 * ldc + c;
            size_t off1 = (size_t)(r0 + 8) * ldc + c;
            if (EPI & 2) {
                float2 q0 = *(const float2*)(res + off0);
                float2 q1 = *(const float2*)(res + off1);
                v01.x += q0.x; v01.y += q0.y;
                v23.x += q1.x; v23.y += q1.y;
            }
            if constexpr (sizeof(OT) == 2) {
                *(__half2*)((__half*)C + off0) = __floats2half2_rn(v01.x, v01.y);
                *(__half2*)((__half*)C + off1) = __floats2half2_rn(v23.x, v23.y);
            } else {
                *(float2*)((float*)C + off0) = v01;
                *(float2*)((float*)C + off1) = v23;
            }
        }
    }
}

// ---------------------------------------------------------------------------
// Sequential MPS recurrence over fp16 M. One WARP per (b,h) chain.
// 8-stage cp.async prefetch (distance 7); lane j owns row j (32 halves=64B);
// h-vector fp32 in smem, double-buffered; fp32 accumulate; tanh.approx.
// ---------------------------------------------------------------------------
__global__ void __launch_bounds__(32, 1) recurrence_kernel(
    const __half* __restrict__ Mg, __half* __restrict__ hs)
{
    __shared__ __align__(16) __half smh[8][32][40];
    __shared__ __align__(16) float hsm[2][32];
    const int j = threadIdx.x;
    const int b = blockIdx.x >> 4;
    const int h = blockIdx.x & 15;
    const __half* Mbh = Mg + ((size_t)h * BSROWS + (size_t)b * SEQ) * 1024;
    const uint32_t sbase = smem_u32(&smh[0][0][0]) + (uint32_t)j * 80;

    // preload tiles 0..6 into stages 0..6
#pragma unroll
    for (int t = 0; t < 7; t++) {
        const __half* src = Mbh + (size_t)t * 1024 + j * 32;
        const uint32_t dst = sbase + (uint32_t)t * 2560;
#pragma unroll
        for (int c = 0; c < 4; c++) cp16(dst + c * 16, src + c * 8);
        asm volatile("cp.async.commit_group;");
    }
    hsm[0][j] = 0.17677669529663688f;   // 1/sqrt(32)
    __syncwarp();

    __half* hsb = hs + ((size_t)b * SEQ) * 512 + h * 32 + j;

    for (int s = 0; s < SEQ; ++s) {
        if (s + 7 < SEQ) {
            const __half* src = Mbh + (size_t)(s + 7) * 1024 + j * 32;
            const uint32_t dst = sbase + (uint32_t)((s + 7) & 7) * 2560;
#pragma unroll
            for (int c = 0; c < 4; c++) cp16(dst + c * 16, src + c * 8);
        }
        asm volatile("cp.async.commit_group;");
        asm volatile("cp.async.wait_group 7;");

        const __half2* row2 = (const __half2*)&smh[s & 7][j][0];
        const float*   hv   = hsm[s & 1];
        float a0 = 0.f, a1 = 0.f, a2 = 0.f, a3 = 0.f;
#pragma unroll
        for (int c = 0; c < 8; c++) {
            float2 m0 = __half22float2(row2[2 * c]);
            float2 m1 = __half22float2(row2[2 * c + 1]);
            float4 hh = *(const float4*)&hv[c * 4];
            a0 = fmaf(hh.x, m0.x, a0);
            a1 = fmaf(hh.y, m0.y, a1);
            a2 = fmaf(hh.z, m1.x, a2);
            a3 = fmaf(hh.w, m1.y, a3);
        }
        float r = tanh_fast((a0 + a1) + (a2 + a3));
        hsm[(s + 1) & 1][j] = r;
        hsb[(size_t)s * 512] = __float2half(r);
        __syncwarp();
    }
}

// ---------------------------------------------------------------------------
// Launch
// ---------------------------------------------------------------------------
extern "C" void kernel_launch(void* const* d_in, const int* in_sizes, int n_in,
                              void* d_out, int out_size)
{
    const float* x     = (const float*)d_in[0];
    const float* ln1_g = (const float*)d_in[1];
    const float* ln1_b = (const float*)d_in[2];
    const float* W_in  = (const float*)d_in[3];
    const float* b_in  = (const float*)d_in[4];
    const float* A     = (const float*)d_in[5];
    const float* W_out = (const float*)d_in[6];
    const float* b_out = (const float*)d_in[7];
    const float* ln2_g = (const float*)d_in[8];
    const float* ln2_b = (const float*)d_in[9];
    const float* W1    = (const float*)d_in[10];
    const float* b1    = (const float*)d_in[11];
    const float* W2    = (const float*)d_in[12];
    const float* b2    = (const float*)d_in[13];
    float* out = (float*)d_out;

    float *x2;
    __half *lnh, *vh, *a2h, *Mh, *hsh, *ffnh, *winh, *wouth, *w1h, *w2h;
    cudaGetSymbolAddress((void**)&lnh,   g_lnh);
    cudaGetSymbolAddress((void**)&vh,    g_vh);
    cudaGetSymbolAddress((void**)&a2h,   g_a2h);
    cudaGetSymbolAddress((void**)&Mh,    g_Mh);
    cudaGetSymbolAddress((void**)&hsh,   g_hsh);
    cudaGetSymbolAddress((void**)&x2,    g_x2);
    cudaGetSymbolAddress((void**)&ffnh,  g_ffnh);
    cudaGetSymbolAddress((void**)&winh,  g_winh);
    cudaGetSymbolAddress((void**)&wouth, g_wouth);
    cudaGetSymbolAddress((void**)&w1h,   g_w1h);
    cudaGetSymbolAddress((void**)&w2h,   g_w2h);

    cudaFuncSetAttribute((const void*)(hgemm<0, __half>), cudaFuncAttributeMaxDynamicSharedMemorySize, HSMEM_BYTES);
    cudaFuncSetAttribute((const void*)(hgemm<1, __half>), cudaFuncAttributeMaxDynamicSharedMemorySize, HSMEM_BYTES);
    cudaFuncSetAttribute((const void*)(hgemm<5, __half>), cudaFuncAttributeMaxDynamicSharedMemorySize, HSMEM_BYTES);
    cudaFuncSetAttribute((const void*)(hgemm<3, float>),  cudaFuncAttributeMaxDynamicSharedMemorySize, HSMEM_BYTES);

    // 1) A rearrange -> fp16
    prep_A_kernel<<<4096, 256>>>(A, a2h);

    // 2) all weight transposes -> fp16 [N][K]
    tconv_all_kernel<<<9728, dim3(32, 8)>>>(W1, w1h, W2, w2h, W_in, winh, W_out, wouth);

    // 3) LN1 -> fp16
    ln_h_kernel<<<BSROWS, 256>>>(x, ln1_g, ln1_b, lnh);

    // 4) v = ln @ W_in + b_in   [8192 x 1024 x 1024]  fp16 out
    hgemm<1, __half><<<dim3(8, 64, 1), 256, HSMEM_BYTES>>>(
        lnh, winh, vh, b_in, nullptr, DIM, DIM, DIM, DIM, 0, 0, 0);

    // 5) M[h] = v[:, h*64:(h+1)*64] @ A2[h]^T   16 heads, [8192 x 1024 x 64]
    hgemm<0, __half><<<dim3(8, 64, NH), 256, HSMEM_BYTES>>>(
        vh, a2h, Mh, nullptr, nullptr, 64, DIM, 64, 1024,
        (size_t)64, (size_t)65536, (size_t)BSROWS * 1024);

    // 6) sequential recurrence -> hs (fp16)
    recurrence_kernel<<<64, 32>>>(Mh, hsh);

    // 7) x2 = x + hs @ W_out + b_out   [8192 x 1024 x 512]  fp32 out
    hgemm<3, float><<<dim3(8, 64, 1), 256, HSMEM_BYTES>>>(
        hsh, wouth, x2, b_out, x, 512, 512, 512, DIM, 0, 0, 0);

    // 8) LN2 -> fp16
    ln_h_kernel<<<BSROWS, 256>>>(x2, ln2_g, ln2_b, lnh);

    // 9) ffn = gelu(lnh @ W1 + b1)  [8192 x 4096 x 1024]  fp16 out
    hgemm<5, __half><<<dim3(32, 64, 1), 256, HSMEM_BYTES>>>(
        lnh, w1h, ffnh, b1, nullptr, DIM, DIM, DIM, DFF, 0, 0, 0);

    // 10) out = x2 + ffnh @ W2 + b2  [8192 x 1024 x 4096]  fp32 out
    hgemm<3, float><<<dim3(8, 64, 1), 256, HSMEM_BYTES>>>(
        ffnh, w2h, out, b2, x2, DFF, DFF, DFF, DIM, 0, 0, 0);
}

// round 10
// speedup vs baseline: 5.7144x; 1.1277x over previous
#include <cuda_runtime.h>
#include <cuda_fp16.h>
#include <math.h>
#include <cstdint>

#define BSROWS 8192
#define SEQ    2048
#define DIM    1024
#define NH     16
#define DFF    4096

// ---------------------------------------------------------------------------
// Scratch (device globals) — fp16 everywhere except the residual stream.
// ---------------------------------------------------------------------------
__device__ __half g_lnh  [8388608];    // LN output (reused LN1/LN2)
__device__ __half g_vh   [8388608];    // v = LN1@W_in + b_in
__device__ __half g_a2h  [1048576];    // A rearranged [h][j*32+i][p]
__device__ __half g_Mh   [134217728];  // M[h][bs][j*32+i]   (268MB)
__device__ __half g_hsh  [4194304];    // recurrence out [bs][H*DH]
__device__ float  g_x2   [8388608];    // x + hs@W_out + b_out (fp32 residual)
__device__ __half g_ffnh [33554432];   // GELU(LN2@W1+b1)
__device__ __half g_winh [1048576];    // W_in^T  [1024][1024]
__device__ __half g_wouth[524288];     // W_out^T [1024][512]
__device__ __half g_w1h  [4194304];    // W1^T    [4096][1024]
__device__ __half g_w2h  [4194304];    // W2^T    [1024][4096]

// ---------------------------------------------------------------------------
// Helpers
// ---------------------------------------------------------------------------
__device__ __forceinline__ uint32_t smem_u32(const void* p) {
    return (uint32_t)__cvta_generic_to_shared(p);
}
__device__ __forceinline__ float gelu_exact(float x) {
    return 0.5f * x * (1.0f + erff(x * 0.70710678118654752f));
}
__device__ __forceinline__ void cp16(uint32_t dst, const void* src) {
    asm volatile("cp.async.cg.shared.global [%0], [%1], 16;" :: "r"(dst), "l"(src));
}
__device__ __forceinline__ float tanh_fast(float x) {
    float r;
    asm("tanh.approx.f32 %0, %1;" : "=f"(r) : "f"(x));
    return r;
}
__device__ __forceinline__ void mma_f16(float* d, const uint32_t* a, const uint32_t* b) {
    asm volatile(
        "mma.sync.aligned.m16n8k16.row.col.f32.f16.f16.f32 "
        "{%0,%1,%2,%3}, {%4,%5,%6,%7}, {%8,%9}, {%0,%1,%2,%3};"
        : "+f"(d[0]), "+f"(d[1]), "+f"(d[2]), "+f"(d[3])
        : "r"(a[0]), "r"(a[1]), "r"(a[2]), "r"(a[3]),
          "r"(b[0]), "r"(b[1]));
}
__device__ __forceinline__ void ldsm4(uint32_t& r0, uint32_t& r1, uint32_t& r2,
                                      uint32_t& r3, uint32_t addr) {
    asm volatile("ldmatrix.sync.aligned.m8n8.x4.shared.b16 {%0,%1,%2,%3}, [%4];"
                 : "=r"(r0), "=r"(r1), "=r"(r2), "=r"(r3) : "r"(addr));
}

// ---------------------------------------------------------------------------
// prep: A[h][i][p][j] -> a2h[h][j*32+i][p]  (fp16)
// ---------------------------------------------------------------------------
__global__ void prep_A_kernel(const float* __restrict__ A, __half* __restrict__ A2) {
    int idx = blockIdx.x * 256 + threadIdx.x;
    int j = idx & 31;
    int p = (idx >> 5) & 63;
    int i = (idx >> 11) & 31;
    int h = idx >> 16;
    A2[(size_t)h * 65536 + (size_t)(j * 32 + i) * 64 + p] = __float2half(A[idx]);
}

// ---------------------------------------------------------------------------
// Merged weight transposes (fp32 [R][C] -> fp16 [C][R]).
// ---------------------------------------------------------------------------
__device__ __forceinline__ void ttile(const float* __restrict__ in,
                                      __half* __restrict__ out,
                                      int R, int C, int bx, int by) {
    __shared__ float t[32][33];
    int tx = threadIdx.x, ty = threadIdx.y;
    int x0 = bx * 32, y0 = by * 32;
#pragma unroll
    for (int j = 0; j < 32; j += 8)
        t[ty + j][tx] = in[(size_t)(y0 + ty + j) * C + x0 + tx];
    __syncthreads();
#pragma unroll
    for (int j = 0; j < 32; j += 8)
        out[(size_t)(x0 + ty + j) * R + y0 + tx] = __float2half(t[tx][ty + j]);
}

__global__ void tconv_all_kernel(const float* __restrict__ W1, __half* __restrict__ w1h,
                                 const float* __restrict__ W2, __half* __restrict__ w2h,
                                 const float* __restrict__ Wi, __half* __restrict__ wih,
                                 const float* __restrict__ Wo, __half* __restrict__ woh)
{
    int t = blockIdx.x;
    if (t < 4096)        ttile(W1, w1h, 1024, 4096, t & 127, t >> 7);
    else if (t < 8192)   { t -= 4096; ttile(W2, w2h, 4096, 1024, t & 31, t >> 5); }
    else if (t < 9216)   { t -= 8192; ttile(Wi, wih, 1024, 1024, t & 31, t >> 5); }
    else                 { t -= 9216; ttile(Wo, woh, 512, 1024, t & 31, t >> 5); }
}

// ---------------------------------------------------------------------------
// LayerNorm (fp32 in, fp16 out).
// ---------------------------------------------------------------------------
__global__ void ln_h_kernel(const float* __restrict__ x, const float* __restrict__ g,
                            const float* __restrict__ b, __half* __restrict__ y) {
    int row = blockIdx.x;
    int tid = threadIdx.x;
    const float* xr = x + (size_t)row * DIM;
    float v[4];
    float s = 0.f, sq = 0.f;
#pragma unroll
    for (int i = 0; i < 4; i++) {
        v[i] = xr[tid + i * 256];
        s  += v[i];
        sq += v[i] * v[i];
    }
#pragma unroll
    for (int o = 16; o > 0; o >>= 1) {
        s  += __shfl_xor_sync(0xffffffffu, s,  o);
        sq += __shfl_xor_sync(0xffffffffu, sq, o);
    }
    __shared__ float ss[8], sqq[8];
    int w = tid >> 5, l = tid & 31;
    if (l == 0) { ss[w] = s; sqq[w] = sq; }
    __syncthreads();
    if (w == 0) {
        s  = (l < 8) ? ss[l]  : 0.f;
        sq = (l < 8) ? sqq[l] : 0.f;
#pragma unroll
        for (int o = 4; o > 0; o >>= 1) {
            s  += __shfl_xor_sync(0xffffffffu, s,  o);
            sq += __shfl_xor_sync(0xffffffffu, sq, o);
        }
        if (l == 0) { ss[0] = s; sqq[0] = sq; }
    }
    __syncthreads();
    s = ss[0]; sq = sqq[0];
    float mean = s * (1.0f / DIM);
    float var  = sq * (1.0f / DIM) - mean * mean;
    float rstd = rsqrtf(var + 1e-5f);
    __half* yr = y + (size_t)row * DIM;
#pragma unroll
    for (int i = 0; i < 4; i++) {
        int c = tid + i * 256;
        yr[c] = __float2half((v[i] - mean) * rstd * g[c] + b[c]);
    }
}

// ---------------------------------------------------------------------------
// fp16 warp-MMA GEMM with ldmatrix fragment loads.
// C[M,N] = A[M,K] @ BT[N,K]^T  (fp32 accumulate)
// CTA 128x128, BK=32, 3-stage cp.async, 8 warps (64x32), mma.m16n8k16.
// SMEM [3][128][40] halves each for A and B (stride 40 -> conflict-free
// ldmatrix: rows at 20-word offsets cover all 32 banks).
// EPI: bit0=bias, bit1=residual(float), bit2=gelu.  OT: __half or float.
// ---------------------------------------------------------------------------
#define HSMEM_BYTES 61440

template <int EPI, typename OT>
__global__ void __launch_bounds__(256, 2) hgemm(
    const __half* __restrict__ A, const __half* __restrict__ BT, OT* __restrict__ C,
    const float* __restrict__ bias, const float* __restrict__ res,
    int K, int lda, int ldb, int ldc,
    size_t batchA, size_t batchB, size_t batchC)
{
    extern __shared__ __half hsm[];
    __half* As = hsm;            // [3][128][40]
    __half* Bs = hsm + 15360;    // [3][128][40]

    A  += (size_t)blockIdx.z * batchA;
    BT += (size_t)blockIdx.z * batchB;
    C  += (size_t)blockIdx.z * batchC;

    const int tid = threadIdx.x;
    const int m0 = blockIdx.y * 128, n0 = blockIdx.x * 128;
    const int wid = tid >> 5, lane = tid & 31;
    const int wm = (wid >> 2) * 64;
    const int wn = (wid & 3) * 32;
    const int gq = lane >> 2, tg = lane & 3;

    const uint32_t sA = smem_u32(As);
    const uint32_t sB = smem_u32(Bs);

    const int row = tid >> 1, half = tid & 1;   // gmem->smem: 2 thr per 64B row

    auto loadA = [&](int st, int k0) {
        const __half* src = A + (size_t)(m0 + row) * lda + k0 + half * 16;
        uint32_t dst = sA + (uint32_t)st * 10240 + (uint32_t)row * 80 + (uint32_t)half * 32;
        cp16(dst, src); cp16(dst + 16, src + 8);
    };
    auto loadB = [&](int st, int k0) {
        const __half* src = BT + (size_t)(n0 + row) * ldb + k0 + half * 16;
        uint32_t dst = sB + (uint32_t)st * 10240 + (uint32_t)row * 80 + (uint32_t)half * 32;
        cp16(dst, src); cp16(dst + 16, src + 8);
    };

    // ldmatrix per-lane byte offsets (within a stage)
    // A x4: m0=rows0-7 kLo, m1=rows8-15 kLo, m2=rows0-7 kHi, m3=rows8-15 kHi
    const int arow_l = (lane & 7) | (((lane >> 3) & 1) << 3);  // 0..15
    const int aseg   = lane >> 4;                              // 0/1 (k half)
    const uint32_t aoffB = (uint32_t)(wm + arow_l) * 80 + (uint32_t)aseg * 16;
    // B x4 (ni pair): m0=rows(p16+0..7) kLo, m1=kHi, m2=rows(p16+8..15) kLo, m3=kHi
    const int brow_l = (lane & 7) + ((lane >> 4) << 3);        // 0..15
    const int bseg   = (lane >> 3) & 1;                        // 0/1 (k half)
    const uint32_t boffB = (uint32_t)(wn + brow_l) * 80 + (uint32_t)bseg * 16;

    float acc[4][4][4];
#pragma unroll
    for (int mi = 0; mi < 4; mi++)
#pragma unroll
        for (int ni = 0; ni < 4; ni++)
#pragma unroll
            for (int q = 0; q < 4; q++) acc[mi][ni][q] = 0.f;

    const int KT = K >> 5;
    loadA(0, 0);  loadB(0, 0);
    asm volatile("cp.async.commit_group;");
    loadA(1, 32); loadB(1, 32);
    asm volatile("cp.async.commit_group;");

    for (int kt = 0; kt < KT; ++kt) {
        const int buf = kt % 3;
        asm volatile("cp.async.wait_group 1;");
        __syncthreads();
        if (kt + 2 < KT) {
            const int st = (kt + 2) % 3;
            loadA(st, (kt + 2) * 32);
            loadB(st, (kt + 2) * 32);
        }
        asm volatile("cp.async.commit_group;");

        const uint32_t aB = sA + (uint32_t)buf * 10240 + aoffB;
        const uint32_t bB = sB + (uint32_t)buf * 10240 + boffB;
#pragma unroll
        for (int kk = 0; kk < 32; kk += 16) {
            uint32_t a[4][4], b[4][2];
#pragma unroll
            for (int mi = 0; mi < 4; mi++)
                ldsm4(a[mi][0], a[mi][1], a[mi][2], a[mi][3],
                      aB + (uint32_t)mi * (16 * 80) + (uint32_t)kk * 2);
#pragma unroll
            for (int p = 0; p < 2; p++)
                ldsm4(b[2 * p][0], b[2 * p][1], b[2 * p + 1][0], b[2 * p + 1][1],
                      bB + (uint32_t)p * (16 * 80) + (uint32_t)kk * 2);
#pragma unroll
            for (int mi = 0; mi < 4; mi++)
#pragma unroll
                for (int ni = 0; ni < 4; ni++)
                    mma_f16(acc[mi][ni], a[mi], b[ni]);
        }
    }

    // epilogue
#pragma unroll
    for (int mi = 0; mi < 4; mi++) {
        const int r0 = m0 + wm + mi * 16 + gq;
#pragma unroll
        for (int ni = 0; ni < 4; ni++) {
            const int c = n0 + wn + ni * 8 + 2 * tg;
            float2 v01 = make_float2(acc[mi][ni][0], acc[mi][ni][1]);
            float2 v23 = make_float2(acc[mi][ni][2], acc[mi][ni][3]);
            if (EPI & 1) {
                float2 bv = *(const float2*)(bias + c);
                v01.x += bv.x; v01.y += bv.y;
                v23.x += bv.x; v23.y += bv.y;
            }
            if (EPI & 4) {
                v01.x = gelu_exact(v01.x); v01.y = gelu_exact(v01.y);
                v23.x = gelu_exact(v23.x); v23.y = gelu_exact(v23.y);
            }
            size_t off0 = (size_t)r0 * ldc + c;
            size_t off1 = (size_t)(r0 + 8) * ldc + c;
            if (EPI & 2) {
                float2 q0 = *(const float2*)(res + off0);
                float2 q1 = *(const float2*)(res + off1);
                v01.x += q0.x; v01.y += q0.y;
                v23.x += q1.x; v23.y += q1.y;
            }
            if constexpr (sizeof(OT) == 2) {
                *(__half2*)((__half*)C + off0) = __floats2half2_rn(v01.x, v01.y);
                *(__half2*)((__half*)C + off1) = __floats2half2_rn(v23.x, v23.y);
            } else {
                *(float2*)((float*)C + off0) = v01;
                *(float2*)((float*)C + off1) = v23;
            }
        }
    }
}

// ---------------------------------------------------------------------------
// Sequential MPS recurrence over fp16 M (unchanged from R9).
// ---------------------------------------------------------------------------
__global__ void __launch_bounds__(32, 1) recurrence_kernel(
    const __half* __restrict__ Mg, __half* __restrict__ hs)
{
    __shared__ __align__(16) __half smh[8][32][40];
    __shared__ __align__(16) float hsm[2][32];
    const int j = threadIdx.x;
    const int b = blockIdx.x >> 4;
    const int h = blockIdx.x & 15;
    const __half* Mbh = Mg + ((size_t)h * BSROWS + (size_t)b * SEQ) * 1024;
    const uint32_t sbase = smem_u32(&smh[0][0][0]) + (uint32_t)j * 80;

#pragma unroll
    for (int t = 0; t < 7; t++) {
        const __half* src = Mbh + (size_t)t * 1024 + j * 32;
        const uint32_t dst = sbase + (uint32_t)t * 2560;
#pragma unroll
        for (int c = 0; c < 4; c++) cp16(dst + c * 16, src + c * 8);
        asm volatile("cp.async.commit_group;");
    }
    hsm[0][j] = 0.17677669529663688f;   // 1/sqrt(32)
    __syncwarp();

    __half* hsb = hs + ((size_t)b * SEQ) * 512 + h * 32 + j;

    for (int s = 0; s < SEQ; ++s) {
        if (s + 7 < SEQ) {
            const __half* src = Mbh + (size_t)(s + 7) * 1024 + j * 32;
            const uint32_t dst = sbase + (uint32_t)((s + 7) & 7) * 2560;
#pragma unroll
            for (int c = 0; c < 4; c++) cp16(dst + c * 16, src + c * 8);
        }
        asm volatile("cp.async.commit_group;");
        asm volatile("cp.async.wait_group 7;");

        const __half2* row2 = (const __half2*)&smh[s & 7][j][0];
        const float*   hv   = hsm[s & 1];
        float a0 = 0.f, a1 = 0.f, a2 = 0.f, a3 = 0.f;
#pragma unroll
        for (int c = 0; c < 8; c++) {
            float2 m0 = __half22float2(row2[2 * c]);
            float2 m1 = __half22float2(row2[2 * c + 1]);
            float4 hh = *(const float4*)&hv[c * 4];
            a0 = fmaf(hh.x, m0.x, a0);
            a1 = fmaf(hh.y, m0.y, a1);
            a2 = fmaf(hh.z, m1.x, a2);
            a3 = fmaf(hh.w, m1.y, a3);
        }
        float r = tanh_fast((a0 + a1) + (a2 + a3));
        hsm[(s + 1) & 1][j] = r;
        hsb[(size_t)s * 512] = __float2half(r);
        __syncwarp();
    }
}

// ---------------------------------------------------------------------------
// Launch
// ---------------------------------------------------------------------------
extern "C" void kernel_launch(void* const* d_in, const int* in_sizes, int n_in,
                              void* d_out, int out_size)
{
    const float* x     = (const float*)d_in[0];
    const float* ln1_g = (const float*)d_in[1];
    const float* ln1_b = (const float*)d_in[2];
    const float* W_in  = (const float*)d_in[3];
    const float* b_in  = (const float*)d_in[4];
    const float* A     = (const float*)d_in[5];
    const float* W_out = (const float*)d_in[6];
    const float* b_out = (const float*)d_in[7];
    const float* ln2_g = (const float*)d_in[8];
    const float* ln2_b = (const float*)d_in[9];
    const float* W1    = (const float*)d_in[10];
    const float* b1    = (const float*)d_in[11];
    const float* W2    = (const float*)d_in[12];
    const float* b2    = (const float*)d_in[13];
    float* out = (float*)d_out;

    float *x2;
    __half *lnh, *vh, *a2h, *Mh, *hsh, *ffnh, *winh, *wouth, *w1h, *w2h;
    cudaGetSymbolAddress((void**)&lnh,   g_lnh);
    cudaGetSymbolAddress((void**)&vh,    g_vh);
    cudaGetSymbolAddress((void**)&a2h,   g_a2h);
    cudaGetSymbolAddress((void**)&Mh,    g_Mh);
    cudaGetSymbolAddress((void**)&hsh,   g_hsh);
    cudaGetSymbolAddress((void**)&x2,    g_x2);
    cudaGetSymbolAddress((void**)&ffnh,  g_ffnh);
    cudaGetSymbolAddress((void**)&winh,  g_winh);
    cudaGetSymbolAddress((void**)&wouth, g_wouth);
    cudaGetSymbolAddress((void**)&w1h,   g_w1h);
    cudaGetSymbolAddress((void**)&w2h,   g_w2h);

    cudaFuncSetAttribute((const void*)(hgemm<0, __half>), cudaFuncAttributeMaxDynamicSharedMemorySize, HSMEM_BYTES);
    cudaFuncSetAttribute((const void*)(hgemm<1, __half>), cudaFuncAttributeMaxDynamicSharedMemorySize, HSMEM_BYTES);
    cudaFuncSetAttribute((const void*)(hgemm<5, __half>), cudaFuncAttributeMaxDynamicSharedMemorySize, HSMEM_BYTES);
    cudaFuncSetAttribute((const void*)(hgemm<3, float>),  cudaFuncAttributeMaxDynamicSharedMemorySize, HSMEM_BYTES);

    // 1) A rearrange -> fp16
    prep_A_kernel<<<4096, 256>>>(A, a2h);

    // 2) all weight transposes -> fp16 [N][K]
    tconv_all_kernel<<<9728, dim3(32, 8)>>>(W1, w1h, W2, w2h, W_in, winh, W_out, wouth);

    // 3) LN1 -> fp16
    ln_h_kernel<<<BSROWS, 256>>>(x, ln1_g, ln1_b, lnh);

    // 4) v = ln @ W_in + b_in   [8192 x 1024 x 1024]  fp16 out
    hgemm<1, __half><<<dim3(8, 64, 1), 256, HSMEM_BYTES>>>(
        lnh, winh, vh, b_in, nullptr, DIM, DIM, DIM, DIM, 0, 0, 0);

    // 5) M[h] = v[:, h*64:(h+1)*64] @ A2[h]^T   16 heads, [8192 x 1024 x 64]
    hgemm<0, __half><<<dim3(8, 64, NH), 256, HSMEM_BYTES>>>(
        vh, a2h, Mh, nullptr, nullptr, 64, DIM, 64, 1024,
        (size_t)64, (size_t)65536, (size_t)BSROWS * 1024);

    // 6) sequential recurrence -> hs (fp16)
    recurrence_kernel<<<64, 32>>>(Mh, hsh);

    // 7) x2 = x + hs @ W_out + b_out   [8192 x 1024 x 512]  fp32 out
    hgemm<3, float><<<dim3(8, 64, 1), 256, HSMEM_BYTES>>>(
        hsh, wouth, x2, b_out, x, 512, 512, 512, DIM, 0, 0, 0);

    // 8) LN2 -> fp16
    ln_h_kernel<<<BSROWS, 256>>>(x2, ln2_g, ln2_b, lnh);

    // 9) ffn = gelu(lnh @ W1 + b1)  [8192 x 4096 x 1024]  fp16 out
    hgemm<5, __half><<<dim3(32, 64, 1), 256, HSMEM_BYTES>>>(
        lnh, w1h, ffnh, b1, nullptr, DIM, DIM, DIM, DFF, 0, 0, 0);

    // 10) out = x2 + ffnh @ W2 + b2  [8192 x 1024 x 4096]  fp32 out
    hgemm<3, float><<<dim3(8, 64, 1), 256, HSMEM_BYTES>>>(
        ffnh, w2h, out, b2, x2, DFF, DFF, DFF, DIM, 0, 0, 0);
}